// round 1
// baseline (speedup 1.0000x reference)
#include <cuda_runtime.h>
#include <cstdint>

#define Bb 8
#define Ss 25
#define Hh 512
#define Ww 512
#define Aa 20
#define Kk 100
#define NMAPS (Bb*Ss)        // 200
#define HWs (Hh*Ww)          // 262144
#define CAP 65536
#define NPART 16

// output layout (all float32, concat of reference tuple, flattened)
#define OFF_SCORES 0
#define OFF_COORDS 20000
#define OFF_VALID  60000
#define OFF_EPAF   80000
#define OFF_ER     1680000
#define OFF_PV     3280000
#define OFF_IP     4880000

__device__ float2 g_part[NMAPS*NPART];
__device__ float g_m[NMAPS];
__device__ float g_Z[NMAPS];
__device__ float g_cut[NMAPS];
__device__ int   g_cnt[NMAPS];
__device__ unsigned long long g_cand[(size_t)NMAPS*CAP];
__device__ int g_selx[NMAPS*Kk];
__device__ int g_sely[NMAPS*Kk];
__device__ int g_selv[NMAPS*Kk];

// ---------------------------------------------------------------------------
// Kernel 1: per-map partial (max, sum exp(v)) over 1/NPART of a map
// ---------------------------------------------------------------------------
__global__ void __launch_bounds__(256) k_reduce(const float* __restrict__ pose) {
    int blk = blockIdx.x;                 // NMAPS*NPART blocks
    int map = blk / NPART, part = blk % NPART;
    const float4* p = (const float4*)(pose + (size_t)map*HWs + (size_t)part*(HWs/NPART));
    int tid = threadIdx.x;
    float m = -3.4e38f;
    float s = 0.f;
#pragma unroll 4
    for (int i = tid; i < (HWs/NPART)/4; i += 256) {
        float4 v = p[i];
        m = fmaxf(fmaxf(m, v.x), fmaxf(v.y, fmaxf(v.z, v.w)));
        s += __expf(v.x) + __expf(v.y) + __expf(v.z) + __expf(v.w);
    }
    for (int o = 16; o; o >>= 1) {
        m = fmaxf(m, __shfl_down_sync(0xFFFFFFFFu, m, o));
        s += __shfl_down_sync(0xFFFFFFFFu, s, o);
    }
    __shared__ float sm[8], ss[8];
    if ((tid & 31) == 0) { sm[tid>>5] = m; ss[tid>>5] = s; }
    __syncthreads();
    if (tid < 8) {
        m = sm[tid]; s = ss[tid];
        for (int o = 4; o; o >>= 1) {
            m = fmaxf(m, __shfl_down_sync(0xFFu, m, o));
            s += __shfl_down_sync(0xFFu, s, o);
        }
        if (tid == 0) g_part[blk] = make_float2(m, s);
    }
}

// ---------------------------------------------------------------------------
// Kernel 2: finalize per-map max m, Z, logit-domain cutoff; reset counters
// ---------------------------------------------------------------------------
__global__ void k_finalize() {
    int map = threadIdx.x;
    if (map >= NMAPS) return;
    float m = -3.4e38f, S0 = 0.f;
#pragma unroll
    for (int i = 0; i < NPART; i++) {
        float2 p = g_part[map*NPART + i];
        m = fmaxf(m, p.x);
        S0 += p.y;
    }
    float Z = S0 * __expf(-m);            // sum exp(x - m)
    g_m[map] = m; g_Z[map] = Z;
    // xhat > thr  <=>  x > m + log(thr * Z); thr = max(2/HW, 0.01/Z)
    float cut = m + fmaxf(__logf(Z * (2.0f / (float)HWs)), -4.6051702f /*log 0.01*/);
    g_cut[map] = cut;
    g_cnt[map] = 0;
}

// ---------------------------------------------------------------------------
// Kernel 3: 3x3 NMS + threshold; push (inv-ordered-value | pixel-index) keys
// ---------------------------------------------------------------------------
__global__ void __launch_bounds__(256) k_nms(const float* __restrict__ pose) {
    int map = blockIdx.y;
    int base = (blockIdx.x * 256 + threadIdx.x) * 4;
    const float* pm = pose + (size_t)map*HWs;
    float cut = g_cut[map];
    float4 v4 = *(const float4*)(pm + base);
    float v[4] = {v4.x, v4.y, v4.z, v4.w};
    int y  = base >> 9;
    int xb = base & 511;
#pragma unroll
    for (int k = 0; k < 4; k++) {
        float vv = v[k];
        if (vv > cut) {
            int x = xb + k;
            bool ok = true;
            for (int dy = -1; dy <= 1 && ok; dy++) {
                int yy = y + dy;
                if (yy < 0 || yy >= Hh) continue;
                for (int dx = -1; dx <= 1; dx++) {
                    int xx = x + dx;
                    if (xx < 0 || xx >= Ww) continue;
                    if (dx == 0 && dy == 0) continue;
                    if (__ldg(pm + yy*Ww + xx) > vv) { ok = false; break; }
                }
            }
            if (ok) {
                int pos = atomicAdd(&g_cnt[map], 1);
                if (pos < CAP) {
                    unsigned u = __float_as_uint(vv);
                    unsigned ord = u ^ ((u >> 31) ? 0xFFFFFFFFu : 0x80000000u);
                    unsigned inv = ~ord;   // smaller key = larger value
                    g_cand[(size_t)map*CAP + pos] =
                        ((unsigned long long)inv << 32) | (unsigned)(y*Ww + x);
                }
            }
        }
    }
}

// ---------------------------------------------------------------------------
// Kernel 4: exact top-K per map (2-round 12-bit radix select + compact + 100x
// block-min). Deterministic despite atomic compaction order (full-key order).
// ---------------------------------------------------------------------------
__global__ void __launch_bounds__(256) k_topk(float* __restrict__ out) {
    int map = blockIdx.x;
    int tid = threadIdx.x;
    int n = g_cnt[map]; if (n > CAP) n = CAP;
    const unsigned long long* cand = g_cand + (size_t)map*CAP;

    __shared__ int hist[4096];
    __shared__ int psum[256];
    __shared__ unsigned long long list[2048];
    __shared__ int sh_T, sh_C, nlist;

    unsigned thr24 = 0xFFFFFFu;
    if (n > Kk) {
        // ---- round 1: bits [63:52] ----
        for (int i = tid; i < 4096; i += 256) hist[i] = 0;
        __syncthreads();
        for (int i = tid; i < n; i += 256)
            atomicAdd(&hist[(int)(cand[i] >> 52)], 1);
        __syncthreads();
        int seg = 0;
        for (int j = 0; j < 16; j++) seg += hist[tid*16 + j];
        psum[tid] = seg;
        __syncthreads();
        if (tid == 0) { int run = 0; for (int t = 0; t < 256; t++) { int tmp = psum[t]; psum[t] = run; run += tmp; } }
        __syncthreads();
        if (psum[tid] < Kk && psum[tid] + seg >= Kk) {
            int c = psum[tid];
            for (int j = 0; j < 16; j++) {
                int h = hist[tid*16 + j];
                if (c + h >= Kk) { sh_T = tid*16 + j; sh_C = c; break; }
                c += h;
            }
        }
        __syncthreads();
        int T = sh_T, C0 = sh_C;
        // ---- round 2: bits [51:40] within bin T ----
        for (int i = tid; i < 4096; i += 256) hist[i] = 0;
        __syncthreads();
        for (int i = tid; i < n; i += 256) {
            unsigned long long key = cand[i];
            if ((int)(key >> 52) == T) atomicAdd(&hist[(int)((key >> 40) & 0xFFF)], 1);
        }
        __syncthreads();
        int need = Kk - C0;
        seg = 0;
        for (int j = 0; j < 16; j++) seg += hist[tid*16 + j];
        psum[tid] = seg;
        __syncthreads();
        if (tid == 0) { int run = 0; for (int t = 0; t < 256; t++) { int tmp = psum[t]; psum[t] = run; run += tmp; } }
        __syncthreads();
        if (psum[tid] < need && psum[tid] + seg >= need) {
            int c = psum[tid];
            for (int j = 0; j < 16; j++) {
                int h = hist[tid*16 + j];
                if (c + h >= need) { sh_T = tid*16 + j; break; }
                c += h;
            }
        }
        __syncthreads();
        thr24 = ((unsigned)T << 12) | (unsigned)sh_T;
    }

    if (tid == 0) nlist = 0;
    __syncthreads();
    for (int i = tid; i < n; i += 256) {
        unsigned long long key = cand[i];
        if ((unsigned)(key >> 40) <= thr24) {
            int p = atomicAdd(&nlist, 1);
            if (p < 2048) list[p] = key;
        }
    }
    __syncthreads();
    int M = min(nlist, 2048);
    float m = g_m[map];
    float invZ = 1.f / g_Z[map];

    __shared__ unsigned long long wkey[8];
    __shared__ int wpos[8];
    for (int slot = 0; slot < Kk; slot++) {
        unsigned long long best = ~0ull; int bpos = -1;
        for (int i = tid; i < M; i += 256) {
            unsigned long long k = list[i];
            if (k < best) { best = k; bpos = i; }
        }
        for (int o = 16; o; o >>= 1) {
            unsigned long long ok = __shfl_down_sync(0xFFFFFFFFu, best, o);
            int op = __shfl_down_sync(0xFFFFFFFFu, bpos, o);
            if (ok < best) { best = ok; bpos = op; }
        }
        if ((tid & 31) == 0) { wkey[tid>>5] = best; wpos[tid>>5] = bpos; }
        __syncthreads();
        if (tid == 0) {
            for (int w = 1; w < 8; w++)
                if (wkey[w] < best) { best = wkey[w]; bpos = wpos[w]; }
            int gx = 0, gy = 0, gv = 0; float sc = 0.f;
            if (best != ~0ull) {
                list[bpos] = ~0ull;
                unsigned idx = (unsigned)(best & 0xFFFFFFFFu);
                gx = idx & 511; gy = idx >> 9;
                unsigned ord = ~(unsigned)(best >> 32);
                unsigned u = (ord & 0x80000000u) ? (ord ^ 0x80000000u) : ~ord;
                float v = __uint_as_float(u);
                sc = __expf(v - m) * invZ;
                gv = 1;
            }
            int o = map*Kk + slot;
            out[OFF_SCORES + o]       = sc;
            out[OFF_COORDS + o*2]     = (float)gx;
            out[OFF_COORDS + o*2 + 1] = (float)gy;
            out[OFF_VALID  + o]       = (float)gv;
            g_selx[o] = gx; g_sely[o] = gy; g_selv[o] = gv;
        }
        __syncthreads();
    }
}

// ---------------------------------------------------------------------------
// Kernel 5: KxK pair edges per (b,a). PAF gathered ONLY for valid pairs
// (R < 20 px): ~0.5% of pairs -> PAF never read densely.
// ---------------------------------------------------------------------------
__global__ void __launch_bounds__(256) k_pairs(const float* __restrict__ paf,
                                               float* __restrict__ out) {
    int ba = blockIdx.x;                  // b*Aa + a
    int a  = ba % Aa;
    int b  = ba / Aa;
    int m1 = b*Ss + a, m2 = m1 + 1;
    __shared__ int x1[Kk], y1[Kk], v1[Kk], x2[Kk], y2[Kk], v2[Kk];
    int tid = threadIdx.x;
    if (tid < Kk) {
        x1[tid] = g_selx[m1*Kk + tid]; y1[tid] = g_sely[m1*Kk + tid]; v1[tid] = g_selv[m1*Kk + tid];
        x2[tid] = g_selx[m2*Kk + tid]; y2[tid] = g_sely[m2*Kk + tid]; v2[tid] = g_selv[m2*Kk + tid];
    }
    __syncthreads();
    const float* pafx = paf + (size_t)(ba*2)*HWs;
    const float* pafy = pafx + HWs;
    size_t eb = (size_t)ba * Kk * Kk;
    size_t ib = (size_t)ba * 2 * Kk * Kk;
    for (int idx = tid; idx < Kk*Kk; idx += 256) {
        int j2 = idx / Kk, j1 = idx - j2*Kk;
        float dx = (float)(x2[j2] - x1[j1]);
        float dy = (float)(y2[j2] - y1[j1]);
        float R = sqrtf(dx*dx + dy*dy);
        bool pv = (R < 20.0f) && v1[j1] && v2[j2];
        float li = 0.f;
        if (pv && R > 0.f) {
            float tvx = dx / R, tvy = dy / R;
            int px1 = x1[j1], py1 = y1[j1], px2 = x2[j2], py2 = y2[j2];
            float acc = 0.f;
#pragma unroll
            for (int t = 0; t < 10; t++) {
                int sx = (px1*(9 - t) + px2*t) / 9;
                int sy = (py1*(9 - t) + py2*t) / 9;
                int off = sy*Ww + sx;
                acc += tvx*__ldg(pafx + off) + tvy*__ldg(pafy + off);
            }
            li = acc * 0.1f;
        }
        out[OFF_EPAF + eb + idx] = li;
        out[OFF_ER   + eb + idx] = pv ? R : 0.f;
        out[OFF_PV   + eb + idx] = pv ? 1.f : 0.f;
        out[OFF_IP   + ib + idx]           = (float)(a*Kk + j1);
        out[OFF_IP   + ib + Kk*Kk + idx]   = (float)((a + 1)*Kk + j2);
    }
}

extern "C" void kernel_launch(void* const* d_in, const int* in_sizes, int n_in,
                              void* d_out, int out_size) {
    const float* pose = (const float*)d_in[0];
    const float* paf  = (const float*)d_in[1];
    float* out = (float*)d_out;
    k_reduce  <<<NMAPS*NPART, 256>>>(pose);
    k_finalize<<<1, 256>>>();
    k_nms     <<<dim3(HWs/1024, NMAPS), 256>>>(pose);
    k_topk    <<<NMAPS, 256>>>(out);
    k_pairs   <<<Bb*Aa, 256>>>(paf, out);
}

// round 2
// speedup vs baseline: 1.0134x; 1.0134x over previous
#include <cuda_runtime.h>
#include <cstdint>

#define Bb 8
#define Ss 25
#define Hh 512
#define Ww 512
#define Aa 20
#define Kk 100
#define NMAPS (Bb*Ss)        // 200
#define HWs (Hh*Ww)          // 262144
#define CAP 65536
#define NPART 16

// output layout (all float32, concat of reference tuple, flattened)
#define OFF_SCORES 0
#define OFF_COORDS 20000
#define OFF_VALID  60000
#define OFF_EPAF   80000
#define OFF_ER     1680000
#define OFF_PV     3280000
#define OFF_IP     4880000

__device__ float2 g_part[NMAPS*NPART];
__device__ float g_m[NMAPS];
__device__ float g_Z[NMAPS];
__device__ float g_cut[NMAPS];
__device__ int   g_cnt[NMAPS];
__device__ unsigned long long g_cand[(size_t)NMAPS*CAP];
__device__ int g_selx[NMAPS*Kk];
__device__ int g_sely[NMAPS*Kk];
__device__ int g_selv[NMAPS*Kk];

// ---------------------------------------------------------------------------
// Packed f32x2 helpers (Blackwell: fma.rn.f32x2 doubles fp32 FMA throughput)
// ---------------------------------------------------------------------------
typedef unsigned long long ull;

__device__ __forceinline__ ull pk2(float lo, float hi) {
    ull r; asm("mov.b64 %0,{%1,%2};" : "=l"(r) : "f"(lo), "f"(hi)); return r;
}
__device__ __forceinline__ ull mul2(ull a, ull b) {
    ull r; asm("mul.rn.f32x2 %0,%1,%2;" : "=l"(r) : "l"(a), "l"(b)); return r;
}
__device__ __forceinline__ ull add2(ull a, ull b) {
    ull r; asm("add.rn.f32x2 %0,%1,%2;" : "=l"(r) : "l"(a), "l"(b)); return r;
}
__device__ __forceinline__ ull fma2(ull a, ull b, ull c) {
    ull r; asm("fma.rn.f32x2 %0,%1,%2,%3;" : "=l"(r) : "l"(a), "l"(b), "l"(c)); return r;
}

// exp(x) for a packed pair, FMA-pipe only (no MUFU).
// y = x*log2e; t = y + 1.5*2^23 (round-to-int in low bits); f = y - (t - M);
// 2^f ~ deg-4 Taylor in (f*ln2) folded into coeffs; exponent via bits add.
__device__ __forceinline__ ull exp2x(ull x) {
    const float L2E  = 1.4426950408889634f;
    const float MGK  = 12582912.0f;          // 1.5 * 2^23
    const float C4 = 0.009618129107628477f;  // (ln2)^4/24
    const float C3 = 0.055504108664821580f;  // (ln2)^3/6
    const float C2 = 0.240226506959100710f;  // (ln2)^2/2
    const float C1 = 0.693147180559945300f;  // ln2
    const float C0 = 1.0f;
    ull y = mul2(x, pk2(L2E, L2E));
    ull t = add2(y, pk2(MGK, MGK));
    ull g = add2(t, pk2(-MGK, -MGK));
    ull f = fma2(g, pk2(-1.f, -1.f), y);
    ull p = fma2(f, pk2(C4, C4), pk2(C3, C3));
    p = fma2(f, p, pk2(C2, C2));
    p = fma2(f, p, pk2(C1, C1));
    p = fma2(f, p, pk2(C0, C0));
    uint2 tb = *(uint2*)&t;
    uint2 pb = *(uint2*)&p;
    pb.x += tb.x << 23;                      // low bits of t hold n (2's comp)
    pb.y += tb.y << 23;
    return *(ull*)&pb;
}

// ---------------------------------------------------------------------------
// Kernel 1: per-map partial (max, sum exp(v)) over 1/NPART of a map
// ---------------------------------------------------------------------------
__global__ void __launch_bounds__(256) k_reduce(const float* __restrict__ pose) {
    int blk = blockIdx.x;                 // NMAPS*NPART blocks
    int map = blk / NPART, part = blk % NPART;
    const float4* p = (const float4*)(pose + (size_t)map*HWs + (size_t)part*(HWs/NPART));
    int tid = threadIdx.x;
    float m = -3.4e38f;
    ull sa = 0, sb = 0;                   // two packed accumulators (ILP)
#pragma unroll 4
    for (int i = tid; i < (HWs/NPART)/4; i += 256) {
        float4 v = p[i];
        m = fmaxf(fmaxf(m, fmaxf(v.x, v.y)), fmaxf(v.z, v.w));
        sa = add2(sa, exp2x(pk2(v.x, v.y)));
        sb = add2(sb, exp2x(pk2(v.z, v.w)));
    }
    ull st = add2(sa, sb);
    float2 sp = *(float2*)&st;
    float s = sp.x + sp.y;
    for (int o = 16; o; o >>= 1) {
        m = fmaxf(m, __shfl_down_sync(0xFFFFFFFFu, m, o));
        s += __shfl_down_sync(0xFFFFFFFFu, s, o);
    }
    __shared__ float sm[8], ss[8];
    if ((tid & 31) == 0) { sm[tid>>5] = m; ss[tid>>5] = s; }
    __syncthreads();
    if (tid < 8) {
        m = sm[tid]; s = ss[tid];
        for (int o = 4; o; o >>= 1) {
            m = fmaxf(m, __shfl_down_sync(0xFFu, m, o));
            s += __shfl_down_sync(0xFFu, s, o);
        }
        if (tid == 0) g_part[blk] = make_float2(m, s);
    }
}

// ---------------------------------------------------------------------------
// Kernel 2: finalize per-map max m, Z, logit-domain cutoff; reset counters
// ---------------------------------------------------------------------------
__global__ void k_finalize() {
    int map = threadIdx.x;
    if (map >= NMAPS) return;
    float m = -3.4e38f, S0 = 0.f;
#pragma unroll
    for (int i = 0; i < NPART; i++) {
        float2 p = g_part[map*NPART + i];
        m = fmaxf(m, p.x);
        S0 += p.y;
    }
    float Z = S0 * __expf(-m);            // sum exp(x - m)
    g_m[map] = m; g_Z[map] = Z;
    // xhat > thr  <=>  x > m + log(thr * Z); thr = max(2/HW, 0.01/Z)
    float cut = m + fmaxf(__logf(Z * (2.0f / (float)HWs)), -4.6051702f /*log 0.01*/);
    g_cut[map] = cut;
    g_cnt[map] = 0;
}

// ---------------------------------------------------------------------------
// Kernel 3: 3x3 NMS + threshold; push (inv-ordered-value | pixel-index) keys
// ---------------------------------------------------------------------------
__global__ void __launch_bounds__(256) k_nms(const float* __restrict__ pose) {
    int map = blockIdx.y;
    int base = (blockIdx.x * 256 + threadIdx.x) * 4;
    const float* pm = pose + (size_t)map*HWs;
    float cut = g_cut[map];
    float4 v4 = *(const float4*)(pm + base);
    float v[4] = {v4.x, v4.y, v4.z, v4.w};
    int y  = base >> 9;
    int xb = base & 511;
#pragma unroll
    for (int k = 0; k < 4; k++) {
        float vv = v[k];
        if (vv > cut) {
            int x = xb + k;
            bool ok = true;
            for (int dy = -1; dy <= 1 && ok; dy++) {
                int yy = y + dy;
                if (yy < 0 || yy >= Hh) continue;
                for (int dx = -1; dx <= 1; dx++) {
                    int xx = x + dx;
                    if (xx < 0 || xx >= Ww) continue;
                    if (dx == 0 && dy == 0) continue;
                    if (__ldg(pm + yy*Ww + xx) > vv) { ok = false; break; }
                }
            }
            if (ok) {
                int pos = atomicAdd(&g_cnt[map], 1);
                if (pos < CAP) {
                    unsigned u = __float_as_uint(vv);
                    unsigned ord = u ^ ((u >> 31) ? 0xFFFFFFFFu : 0x80000000u);
                    unsigned inv = ~ord;   // smaller key = larger value
                    g_cand[(size_t)map*CAP + pos] =
                        ((unsigned long long)inv << 32) | (unsigned)(y*Ww + x);
                }
            }
        }
    }
}

// ---------------------------------------------------------------------------
// Kernel 4: exact top-K per map (2-round 12-bit radix select + compact + 100x
// block-min). Fast path when no candidate survives the thresholds.
// ---------------------------------------------------------------------------
__global__ void __launch_bounds__(256) k_topk(float* __restrict__ out) {
    int map = blockIdx.x;
    int tid = threadIdx.x;
    int n = g_cnt[map]; if (n > CAP) n = CAP;
    const unsigned long long* cand = g_cand + (size_t)map*CAP;

    if (n == 0) {
        // empty mask: reference yields scores=0, coords=(0,0), valid=false
        if (tid < Kk) {
            int o = map*Kk + tid;
            out[OFF_SCORES + o]       = 0.f;
            out[OFF_COORDS + o*2]     = 0.f;
            out[OFF_COORDS + o*2 + 1] = 0.f;
            out[OFF_VALID  + o]       = 0.f;
            g_selx[o] = 0; g_sely[o] = 0; g_selv[o] = 0;
        }
        return;
    }

    __shared__ int hist[4096];
    __shared__ int psum[256];
    __shared__ unsigned long long list[2048];
    __shared__ int sh_T, sh_C, nlist;

    unsigned thr24 = 0xFFFFFFu;
    if (n > Kk) {
        // ---- round 1: bits [63:52] ----
        for (int i = tid; i < 4096; i += 256) hist[i] = 0;
        __syncthreads();
        for (int i = tid; i < n; i += 256)
            atomicAdd(&hist[(int)(cand[i] >> 52)], 1);
        __syncthreads();
        int seg = 0;
        for (int j = 0; j < 16; j++) seg += hist[tid*16 + j];
        psum[tid] = seg;
        __syncthreads();
        if (tid == 0) { int run = 0; for (int t = 0; t < 256; t++) { int tmp = psum[t]; psum[t] = run; run += tmp; } }
        __syncthreads();
        if (psum[tid] < Kk && psum[tid] + seg >= Kk) {
            int c = psum[tid];
            for (int j = 0; j < 16; j++) {
                int h = hist[tid*16 + j];
                if (c + h >= Kk) { sh_T = tid*16 + j; sh_C = c; break; }
                c += h;
            }
        }
        __syncthreads();
        int T = sh_T, C0 = sh_C;
        // ---- round 2: bits [51:40] within bin T ----
        for (int i = tid; i < 4096; i += 256) hist[i] = 0;
        __syncthreads();
        for (int i = tid; i < n; i += 256) {
            unsigned long long key = cand[i];
            if ((int)(key >> 52) == T) atomicAdd(&hist[(int)((key >> 40) & 0xFFF)], 1);
        }
        __syncthreads();
        int need = Kk - C0;
        seg = 0;
        for (int j = 0; j < 16; j++) seg += hist[tid*16 + j];
        psum[tid] = seg;
        __syncthreads();
        if (tid == 0) { int run = 0; for (int t = 0; t < 256; t++) { int tmp = psum[t]; psum[t] = run; run += tmp; } }
        __syncthreads();
        if (psum[tid] < need && psum[tid] + seg >= need) {
            int c = psum[tid];
            for (int j = 0; j < 16; j++) {
                int h = hist[tid*16 + j];
                if (c + h >= need) { sh_T = tid*16 + j; break; }
                c += h;
            }
        }
        __syncthreads();
        thr24 = ((unsigned)T << 12) | (unsigned)sh_T;
    }

    if (tid == 0) nlist = 0;
    __syncthreads();
    for (int i = tid; i < n; i += 256) {
        unsigned long long key = cand[i];
        if ((unsigned)(key >> 40) <= thr24) {
            int p = atomicAdd(&nlist, 1);
            if (p < 2048) list[p] = key;
        }
    }
    __syncthreads();
    int M = min(nlist, 2048);
    float m = g_m[map];
    float invZ = 1.f / g_Z[map];

    __shared__ unsigned long long wkey[8];
    __shared__ int wpos[8];
    for (int slot = 0; slot < Kk; slot++) {
        unsigned long long best = ~0ull; int bpos = -1;
        for (int i = tid; i < M; i += 256) {
            unsigned long long k = list[i];
            if (k < best) { best = k; bpos = i; }
        }
        for (int o = 16; o; o >>= 1) {
            unsigned long long ok = __shfl_down_sync(0xFFFFFFFFu, best, o);
            int op = __shfl_down_sync(0xFFFFFFFFu, bpos, o);
            if (ok < best) { best = ok; bpos = op; }
        }
        if ((tid & 31) == 0) { wkey[tid>>5] = best; wpos[tid>>5] = bpos; }
        __syncthreads();
        if (tid == 0) {
            for (int w = 1; w < 8; w++)
                if (wkey[w] < best) { best = wkey[w]; bpos = wpos[w]; }
            int gx = 0, gy = 0, gv = 0; float sc = 0.f;
            if (best != ~0ull) {
                list[bpos] = ~0ull;
                unsigned idx = (unsigned)(best & 0xFFFFFFFFu);
                gx = idx & 511; gy = idx >> 9;
                unsigned ord = ~(unsigned)(best >> 32);
                unsigned u = (ord & 0x80000000u) ? (ord ^ 0x80000000u) : ~ord;
                float v = __uint_as_float(u);
                sc = __expf(v - m) * invZ;
                gv = 1;
            }
            int o = map*Kk + slot;
            out[OFF_SCORES + o]       = sc;
            out[OFF_COORDS + o*2]     = (float)gx;
            out[OFF_COORDS + o*2 + 1] = (float)gy;
            out[OFF_VALID  + o]       = (float)gv;
            g_selx[o] = gx; g_sely[o] = gy; g_selv[o] = gv;
        }
        __syncthreads();
    }
}

// ---------------------------------------------------------------------------
// Kernel 5: KxK pair edges per (b,a). PAF gathered ONLY for valid pairs
// (R < 20 px) -> PAF never read densely.
// ---------------------------------------------------------------------------
__global__ void __launch_bounds__(256) k_pairs(const float* __restrict__ paf,
                                               float* __restrict__ out) {
    int ba = blockIdx.x;                  // b*Aa + a
    int a  = ba % Aa;
    int b  = ba / Aa;
    int m1 = b*Ss + a, m2 = m1 + 1;
    __shared__ int x1[Kk], y1[Kk], v1[Kk], x2[Kk], y2[Kk], v2[Kk];
    int tid = threadIdx.x;
    if (tid < Kk) {
        x1[tid] = g_selx[m1*Kk + tid]; y1[tid] = g_sely[m1*Kk + tid]; v1[tid] = g_selv[m1*Kk + tid];
        x2[tid] = g_selx[m2*Kk + tid]; y2[tid] = g_sely[m2*Kk + tid]; v2[tid] = g_selv[m2*Kk + tid];
    }
    __syncthreads();
    const float* pafx = paf + (size_t)(ba*2)*HWs;
    const float* pafy = pafx + HWs;
    size_t eb = (size_t)ba * Kk * Kk;
    size_t ib = (size_t)ba * 2 * Kk * Kk;
    for (int idx = tid; idx < Kk*Kk; idx += 256) {
        int j2 = idx / Kk, j1 = idx - j2*Kk;
        float dx = (float)(x2[j2] - x1[j1]);
        float dy = (float)(y2[j2] - y1[j1]);
        float R = sqrtf(dx*dx + dy*dy);
        bool pv = (R < 20.0f) && v1[j1] && v2[j2];
        float li = 0.f;
        if (pv && R > 0.f) {
            float tvx = dx / R, tvy = dy / R;
            int px1 = x1[j1], py1 = y1[j1], px2 = x2[j2], py2 = y2[j2];
            float acc = 0.f;
#pragma unroll
            for (int t = 0; t < 10; t++) {
                int sx = (px1*(9 - t) + px2*t) / 9;
                int sy = (py1*(9 - t) + py2*t) / 9;
                int off = sy*Ww + sx;
                acc += tvx*__ldg(pafx + off) + tvy*__ldg(pafy + off);
            }
            li = acc * 0.1f;
        }
        out[OFF_EPAF + eb + idx] = li;
        out[OFF_ER   + eb + idx] = pv ? R : 0.f;
        out[OFF_PV   + eb + idx] = pv ? 1.f : 0.f;
        out[OFF_IP   + ib + idx]           = (float)(a*Kk + j1);
        out[OFF_IP   + ib + Kk*Kk + idx]   = (float)((a + 1)*Kk + j2);
    }
}

extern "C" void kernel_launch(void* const* d_in, const int* in_sizes, int n_in,
                              void* d_out, int out_size) {
    const float* pose = (const float*)d_in[0];
    const float* paf  = (const float*)d_in[1];
    float* out = (float*)d_out;
    k_reduce  <<<NMAPS*NPART, 256>>>(pose);
    k_finalize<<<1, 256>>>();
    k_nms     <<<dim3(HWs/1024, NMAPS), 256>>>(pose);
    k_topk    <<<NMAPS, 256>>>(out);
    k_pairs   <<<Bb*Aa, 256>>>(paf, out);
}

// round 3
// speedup vs baseline: 1.0499x; 1.0360x over previous
#include <cuda_runtime.h>
#include <cuda_fp16.h>
#include <cstdint>

#define Bb 8
#define Ss 25
#define Hh 512
#define Ww 512
#define Aa 20
#define Kk 100
#define NMAPS (Bb*Ss)        // 200
#define HWs (Hh*Ww)          // 262144
#define CAP 65536
#define NPART 16

// output layout (all float32, concat of reference tuple, flattened)
#define OFF_SCORES 0
#define OFF_COORDS 20000
#define OFF_VALID  60000
#define OFF_EPAF   80000
#define OFF_ER     1680000
#define OFF_PV     3280000
#define OFF_IP     4880000

typedef unsigned long long ull;

__device__ float2 g_part[NMAPS*NPART];
__device__ float g_m[NMAPS];
__device__ float g_Z[NMAPS];
__device__ float g_cut[NMAPS];
__device__ int   g_cnt[NMAPS];
__device__ ull   g_cand[(size_t)NMAPS*CAP];
__device__ int g_selx[NMAPS*Kk];
__device__ int g_sely[NMAPS*Kk];
__device__ int g_selv[NMAPS*Kk];

__device__ __forceinline__ unsigned h2ex2(unsigned a) {
    unsigned r;
    asm("ex2.approx.f16x2 %0,%1;" : "=r"(r) : "r"(a));
    return r;
}
__device__ __forceinline__ unsigned hadd2u(unsigned a, unsigned b) {
    unsigned r;
    asm("add.rn.f16x2 %0,%1,%2;" : "=r"(r) : "r"(a), "r"(b));
    return r;
}
__device__ __forceinline__ unsigned pack_h2(float lo, float hi) {
    unsigned r;
    asm("cvt.rn.f16x2.f32 %0,%1,%2;" : "=r"(r) : "f"(hi), "f"(lo));
    return r;
}

// ---------------------------------------------------------------------------
// Kernel 1: per-map partial (max, sum exp(v)). exp via ex2.approx.f16x2:
// 1 MUFU op per 2 elements. fp16 rounding errors are random-sign; the Z sum
// averages them to ~1e-5 relative.
// ---------------------------------------------------------------------------
__global__ void __launch_bounds__(256) k_reduce(const float* __restrict__ pose) {
    int blk = blockIdx.x;                 // NMAPS*NPART blocks
    int map = blk / NPART, part = blk % NPART;
    const float4* p = (const float4*)(pose + (size_t)map*HWs + (size_t)part*(HWs/NPART));
    int tid = threadIdx.x;
    const float L2E = 1.4426950408889634f;
    float m = -3.4e38f;
    unsigned a0 = 0u, a1 = 0u;            // f16x2 accumulators (16 adds each: safe)
#pragma unroll
    for (int c = 0; c < 16; c++) {
        float4 v = p[tid + 256*c];
        m = fmaxf(fmaxf(m, fmaxf(v.x, v.y)), fmaxf(v.z, v.w));
        unsigned y0 = pack_h2(v.x*L2E, v.y*L2E);
        unsigned y1 = pack_h2(v.z*L2E, v.w*L2E);
        a0 = hadd2u(a0, h2ex2(y0));
        a1 = hadd2u(a1, h2ex2(y1));
    }
    __half2 h0 = *(__half2*)&a0, h1 = *(__half2*)&a1;
    float2 f0 = __half22float2(h0), f1 = __half22float2(h1);
    float s = (f0.x + f0.y) + (f1.x + f1.y);
    for (int o = 16; o; o >>= 1) {
        m = fmaxf(m, __shfl_down_sync(0xFFFFFFFFu, m, o));
        s += __shfl_down_sync(0xFFFFFFFFu, s, o);
    }
    __shared__ float sm[8], ss[8];
    if ((tid & 31) == 0) { sm[tid>>5] = m; ss[tid>>5] = s; }
    __syncthreads();
    if (tid < 8) {
        m = sm[tid]; s = ss[tid];
        for (int o = 4; o; o >>= 1) {
            m = fmaxf(m, __shfl_down_sync(0xFFu, m, o));
            s += __shfl_down_sync(0xFFu, s, o);
        }
        if (tid == 0) g_part[blk] = make_float2(m, s);
    }
}

// ---------------------------------------------------------------------------
// Kernel 2: finalize per-map max m, Z, logit-domain cutoff; reset counters
// ---------------------------------------------------------------------------
__global__ void k_finalize() {
    int map = threadIdx.x;
    if (map >= NMAPS) return;
    float m = -3.4e38f, S0 = 0.f;
#pragma unroll
    for (int i = 0; i < NPART; i++) {
        float2 p = g_part[map*NPART + i];
        m = fmaxf(m, p.x);
        S0 += p.y;
    }
    float Z = S0 * __expf(-m);            // sum exp(x - m)
    g_m[map] = m; g_Z[map] = Z;
    // xhat > thr  <=>  x > m + log(thr * Z); thr = max(2/HW, 0.01/Z)
    float cut = m + fmaxf(__logf(Z * (2.0f / (float)HWs)), -4.6051702f /*log 0.01*/);
    g_cut[map] = cut;
    g_cnt[map] = 0;
}

// ---------------------------------------------------------------------------
// Kernel 3: 3x3 NMS + threshold; push (inv-ordered-value | pixel-index) keys
// ---------------------------------------------------------------------------
__global__ void __launch_bounds__(256) k_nms(const float* __restrict__ pose) {
    int map = blockIdx.y;
    int base = (blockIdx.x * 256 + threadIdx.x) * 4;
    const float* pm = pose + (size_t)map*HWs;
    float cut = g_cut[map];
    float4 v4 = *(const float4*)(pm + base);
    float mx4 = fmaxf(fmaxf(v4.x, v4.y), fmaxf(v4.z, v4.w));
    if (mx4 <= cut) return;
    float v[4] = {v4.x, v4.y, v4.z, v4.w};
    int y  = base >> 9;
    int xb = base & 511;
#pragma unroll
    for (int k = 0; k < 4; k++) {
        float vv = v[k];
        if (vv > cut) {
            int x = xb + k;
            bool ok = true;
            for (int dy = -1; dy <= 1 && ok; dy++) {
                int yy = y + dy;
                if (yy < 0 || yy >= Hh) continue;
                for (int dx = -1; dx <= 1; dx++) {
                    int xx = x + dx;
                    if (xx < 0 || xx >= Ww) continue;
                    if (dx == 0 && dy == 0) continue;
                    if (__ldg(pm + yy*Ww + xx) > vv) { ok = false; break; }
                }
            }
            if (ok) {
                int pos = atomicAdd(&g_cnt[map], 1);
                if (pos < CAP) {
                    unsigned u = __float_as_uint(vv);
                    unsigned ord = u ^ ((u >> 31) ? 0xFFFFFFFFu : 0x80000000u);
                    unsigned inv = ~ord;   // smaller key = larger value
                    g_cand[(size_t)map*CAP + pos] =
                        ((ull)inv << 32) | (unsigned)(y*Ww + x);
                }
            }
        }
    }
}

// ---------------------------------------------------------------------------
// Kernel 4: exact top-K per map. 2-round 12-bit radix select -> compact
// (~100-200 keys) -> rank-scatter (each key computes its exact rank and
// writes slot 'rank' directly; keys unique so ranks are a permutation).
// ---------------------------------------------------------------------------
__global__ void __launch_bounds__(256) k_topk(float* __restrict__ out) {
    int map = blockIdx.x;
    int tid = threadIdx.x;
    int n = g_cnt[map]; if (n > CAP) n = CAP;
    const ull* cand = g_cand + (size_t)map*CAP;

    __shared__ int hist[4096];
    __shared__ int psum[256];
    __shared__ ull list[2048];
    __shared__ int sh_T, sh_C, nlist;

    unsigned thr24 = 0xFFFFFFu;
    if (n > Kk) {
        // ---- round 1: bits [63:52] ----
        for (int i = tid; i < 4096; i += 256) hist[i] = 0;
        __syncthreads();
#pragma unroll 4
        for (int i = tid; i < n; i += 256)
            atomicAdd(&hist[(int)(cand[i] >> 52)], 1);
        __syncthreads();
        int seg = 0;
        for (int j = 0; j < 16; j++) seg += hist[tid*16 + j];
        psum[tid] = seg;
        __syncthreads();
        if (tid == 0) { int run = 0; for (int t = 0; t < 256; t++) { int tmp = psum[t]; psum[t] = run; run += tmp; } }
        __syncthreads();
        if (psum[tid] < Kk && psum[tid] + seg >= Kk) {
            int c = psum[tid];
            for (int j = 0; j < 16; j++) {
                int h = hist[tid*16 + j];
                if (c + h >= Kk) { sh_T = tid*16 + j; sh_C = c; break; }
                c += h;
            }
        }
        __syncthreads();
        int T = sh_T, C0 = sh_C;
        // ---- round 2: bits [51:40] within bin T ----
        for (int i = tid; i < 4096; i += 256) hist[i] = 0;
        __syncthreads();
#pragma unroll 4
        for (int i = tid; i < n; i += 256) {
            ull key = cand[i];
            if ((int)(key >> 52) == T) atomicAdd(&hist[(int)((key >> 40) & 0xFFF)], 1);
        }
        __syncthreads();
        int need = Kk - C0;
        seg = 0;
        for (int j = 0; j < 16; j++) seg += hist[tid*16 + j];
        psum[tid] = seg;
        __syncthreads();
        if (tid == 0) { int run = 0; for (int t = 0; t < 256; t++) { int tmp = psum[t]; psum[t] = run; run += tmp; } }
        __syncthreads();
        if (psum[tid] < need && psum[tid] + seg >= need) {
            int c = psum[tid];
            for (int j = 0; j < 16; j++) {
                int h = hist[tid*16 + j];
                if (c + h >= need) { sh_T = tid*16 + j; break; }
                c += h;
            }
        }
        __syncthreads();
        thr24 = ((unsigned)T << 12) | (unsigned)sh_T;
    }

    if (tid == 0) nlist = 0;
    __syncthreads();
#pragma unroll 4
    for (int i = tid; i < n; i += 256) {
        ull key = cand[i];
        if ((unsigned)(key >> 40) <= thr24) {
            int p = atomicAdd(&nlist, 1);
            if (p < 2048) list[p] = key;
        }
    }
    __syncthreads();
    int M = min(nlist, 2048);
    float m = g_m[map];
    float invZ = 1.f / g_Z[map];

    // rank-scatter: element t's rank = #(keys < key_t); write slot 'rank'.
    for (int t = tid; t < M; t += 256) {
        ull k = list[t];
        int rank = 0;
        for (int j = 0; j < M; j++) rank += (list[j] < k);
        if (rank < Kk) {
            unsigned idx = (unsigned)(k & 0xFFFFFFFFu);
            int gx = idx & 511, gy = idx >> 9;
            unsigned ord = ~(unsigned)(k >> 32);
            unsigned u = (ord & 0x80000000u) ? (ord ^ 0x80000000u) : ~ord;
            float v = __uint_as_float(u);
            float sc = __expf(v - m) * invZ;
            int o = map*Kk + rank;
            out[OFF_SCORES + o]       = sc;
            out[OFF_COORDS + o*2]     = (float)gx;
            out[OFF_COORDS + o*2 + 1] = (float)gy;
            out[OFF_VALID  + o]       = 1.f;
            g_selx[o] = gx; g_sely[o] = gy; g_selv[o] = 1;
        }
    }
    // default-fill empty slots [M, Kk)
    if (tid >= M && tid < Kk) {
        int o = map*Kk + tid;
        out[OFF_SCORES + o]       = 0.f;
        out[OFF_COORDS + o*2]     = 0.f;
        out[OFF_COORDS + o*2 + 1] = 0.f;
        out[OFF_VALID  + o]       = 0.f;
        g_selx[o] = 0; g_sely[o] = 0; g_selv[o] = 0;
    }
}

// ---------------------------------------------------------------------------
// Kernel 5: KxK pair edges per (b,a). PAF gathered ONLY for valid pairs
// (R < 20 px) -> PAF never read densely.
// ---------------------------------------------------------------------------
__global__ void __launch_bounds__(256) k_pairs(const float* __restrict__ paf,
                                               float* __restrict__ out) {
    int ba = blockIdx.x;                  // b*Aa + a
    int a  = ba % Aa;
    int b  = ba / Aa;
    int m1 = b*Ss + a, m2 = m1 + 1;
    __shared__ int x1[Kk], y1[Kk], v1[Kk], x2[Kk], y2[Kk], v2[Kk];
    int tid = threadIdx.x;
    if (tid < Kk) {
        x1[tid] = g_selx[m1*Kk + tid]; y1[tid] = g_sely[m1*Kk + tid]; v1[tid] = g_selv[m1*Kk + tid];
        x2[tid] = g_selx[m2*Kk + tid]; y2[tid] = g_sely[m2*Kk + tid]; v2[tid] = g_selv[m2*Kk + tid];
    }
    __syncthreads();
    const float* pafx = paf + (size_t)(ba*2)*HWs;
    const float* pafy = pafx + HWs;
    size_t eb = (size_t)ba * Kk * Kk;
    size_t ib = (size_t)ba * 2 * Kk * Kk;
    for (int idx = tid; idx < Kk*Kk; idx += 256) {
        int j2 = idx / Kk, j1 = idx - j2*Kk;
        float dx = (float)(x2[j2] - x1[j1]);
        float dy = (float)(y2[j2] - y1[j1]);
        float R = sqrtf(dx*dx + dy*dy);
        bool pv = (R < 20.0f) && v1[j1] && v2[j2];
        float li = 0.f;
        if (pv && R > 0.f) {
            float tvx = dx / R, tvy = dy / R;
            int px1 = x1[j1], py1 = y1[j1], px2 = x2[j2], py2 = y2[j2];
            float acc = 0.f;
#pragma unroll
            for (int t = 0; t < 10; t++) {
                int sx = (px1*(9 - t) + px2*t) / 9;
                int sy = (py1*(9 - t) + py2*t) / 9;
                int off = sy*Ww + sx;
                acc += tvx*__ldg(pafx + off) + tvy*__ldg(pafy + off);
            }
            li = acc * 0.1f;
        }
        out[OFF_EPAF + eb + idx] = li;
        out[OFF_ER   + eb + idx] = pv ? R : 0.f;
        out[OFF_PV   + eb + idx] = pv ? 1.f : 0.f;
        out[OFF_IP   + ib + idx]           = (float)(a*Kk + j1);
        out[OFF_IP   + ib + Kk*Kk + idx]   = (float)((a + 1)*Kk + j2);
    }
}

extern "C" void kernel_launch(void* const* d_in, const int* in_sizes, int n_in,
                              void* d_out, int out_size) {
    const float* pose = (const float*)d_in[0];
    const float* paf  = (const float*)d_in[1];
    float* out = (float*)d_out;
    k_reduce  <<<NMAPS*NPART, 256>>>(pose);
    k_finalize<<<1, 256>>>();
    k_nms     <<<dim3(HWs/1024, NMAPS), 256>>>(pose);
    k_topk    <<<NMAPS, 256>>>(out);
    k_pairs   <<<Bb*Aa, 256>>>(paf, out);
}

// round 4
// speedup vs baseline: 4.4156x; 4.2058x over previous
#include <cuda_runtime.h>
#include <cuda_fp16.h>
#include <cstdint>

#define Bb 8
#define Ss 25
#define Hh 512
#define Ww 512
#define Aa 20
#define Kk 100
#define NMAPS (Bb*Ss)        // 200
#define HWs (Hh*Ww)          // 262144
#define CAP 65536
#define NPART 16

// output layout (all float32, concat of reference tuple, flattened)
#define OFF_SCORES 0
#define OFF_COORDS 20000
#define OFF_VALID  60000
#define OFF_EPAF   80000
#define OFF_ER     1680000
#define OFF_PV     3280000
#define OFF_IP     4880000

typedef unsigned long long ull;

__device__ float2 g_part[NMAPS*NPART];
__device__ float g_m[NMAPS];
__device__ float g_Z[NMAPS];
__device__ float g_cut[NMAPS];
__device__ int   g_cnt[NMAPS];
__device__ ull   g_cand[(size_t)NMAPS*CAP];
__device__ int g_selx[NMAPS*Kk];
__device__ int g_sely[NMAPS*Kk];
__device__ int g_selv[NMAPS*Kk];

__device__ __forceinline__ unsigned h2ex2(unsigned a) {
    unsigned r;
    asm("ex2.approx.f16x2 %0,%1;" : "=r"(r) : "r"(a));
    return r;
}
__device__ __forceinline__ unsigned hadd2u(unsigned a, unsigned b) {
    unsigned r;
    asm("add.rn.f16x2 %0,%1,%2;" : "=r"(r) : "r"(a), "r"(b));
    return r;
}
__device__ __forceinline__ unsigned pack_h2(float lo, float hi) {
    unsigned r;
    asm("cvt.rn.f16x2.f32 %0,%1,%2;" : "=r"(r) : "f"(hi), "f"(lo));
    return r;
}

// ---------------------------------------------------------------------------
// Kernel 1: per-map partial (max, sum exp(v)). exp via ex2.approx.f16x2.
// ---------------------------------------------------------------------------
__global__ void __launch_bounds__(256) k_reduce(const float* __restrict__ pose) {
    int blk = blockIdx.x;                 // NMAPS*NPART blocks
    int map = blk / NPART, part = blk % NPART;
    const float4* p = (const float4*)(pose + (size_t)map*HWs + (size_t)part*(HWs/NPART));
    int tid = threadIdx.x;
    const float L2E = 1.4426950408889634f;
    float m = -3.4e38f;
    unsigned a0 = 0u, a1 = 0u;            // f16x2 accumulators (16 adds each)
#pragma unroll
    for (int c = 0; c < 16; c++) {
        float4 v = p[tid + 256*c];
        m = fmaxf(fmaxf(m, fmaxf(v.x, v.y)), fmaxf(v.z, v.w));
        unsigned y0 = pack_h2(v.x*L2E, v.y*L2E);
        unsigned y1 = pack_h2(v.z*L2E, v.w*L2E);
        a0 = hadd2u(a0, h2ex2(y0));
        a1 = hadd2u(a1, h2ex2(y1));
    }
    __half2 h0 = *(__half2*)&a0, h1 = *(__half2*)&a1;
    float2 f0 = __half22float2(h0), f1 = __half22float2(h1);
    float s = (f0.x + f0.y) + (f1.x + f1.y);
    for (int o = 16; o; o >>= 1) {
        m = fmaxf(m, __shfl_down_sync(0xFFFFFFFFu, m, o));
        s += __shfl_down_sync(0xFFFFFFFFu, s, o);
    }
    __shared__ float sm[8], ss[8];
    if ((tid & 31) == 0) { sm[tid>>5] = m; ss[tid>>5] = s; }
    __syncthreads();
    if (tid < 8) {
        m = sm[tid]; s = ss[tid];
        for (int o = 4; o; o >>= 1) {
            m = fmaxf(m, __shfl_down_sync(0xFFu, m, o));
            s += __shfl_down_sync(0xFFu, s, o);
        }
        if (tid == 0) g_part[blk] = make_float2(m, s);
    }
}

// ---------------------------------------------------------------------------
// Kernel 2: finalize per-map max m, Z, logit-domain cutoff; reset counters
// ---------------------------------------------------------------------------
__global__ void k_finalize() {
    int map = threadIdx.x;
    if (map >= NMAPS) return;
    float m = -3.4e38f, S0 = 0.f;
#pragma unroll
    for (int i = 0; i < NPART; i++) {
        float2 p = g_part[map*NPART + i];
        m = fmaxf(m, p.x);
        S0 += p.y;
    }
    float Z = S0 * __expf(-m);            // sum exp(x - m)
    g_m[map] = m; g_Z[map] = Z;
    // xhat > thr  <=>  x > m + log(thr * Z); thr = max(2/HW, 0.01/Z)
    float cut = m + fmaxf(__logf(Z * (2.0f / (float)HWs)), -4.6051702f /*log 0.01*/);
    g_cut[map] = cut;
    g_cnt[map] = 0;
}

// ---------------------------------------------------------------------------
// Kernel 3: 3x3 NMS + threshold. Branchless unrolled neighbor test,
// float4-level gate, block-aggregated candidate push (1 global atomic/block).
// ---------------------------------------------------------------------------
__global__ void __launch_bounds__(256) k_nms(const float* __restrict__ pose) {
    int map = blockIdx.y;
    int tid = threadIdx.x;
    int base = (blockIdx.x * 256 + tid) * 4;
    const float* pm = pose + (size_t)map*HWs;
    float cut = g_cut[map];

    __shared__ ull stage[768];
    __shared__ int s_cnt, s_base;
    if (tid == 0) s_cnt = 0;
    __syncthreads();

    float4 v4 = *(const float4*)(pm + base);
    float v[4] = {v4.x, v4.y, v4.z, v4.w};
    float mx4 = fmaxf(fmaxf(v4.x, v4.y), fmaxf(v4.z, v4.w));

    if (mx4 > cut) {
        int y  = base >> 9;
        int xb = base & 511;
        const float* r1 = pm + y*Ww;
        bool interior = (y > 0) & (y < Hh-1) & (xb > 0) & (xb < Ww-4);
        if (interior) {
            const float* r0 = r1 - Ww;
            const float* r2 = r1 + Ww;
#pragma unroll
            for (int k = 0; k < 4; k++) {
                float vv = v[k];
                if (vv > cut) {
                    int x = xb + k;
                    float left  = (k > 0) ? v[k-1] : __ldg(r1 + x - 1);
                    float right = (k < 3) ? v[k+1] : __ldg(r1 + x + 1);
                    float nmx = fmaxf(left, right);
                    nmx = fmaxf(nmx, fmaxf(__ldg(r0 + x - 1),
                                 fmaxf(__ldg(r0 + x), __ldg(r0 + x + 1))));
                    nmx = fmaxf(nmx, fmaxf(__ldg(r2 + x - 1),
                                 fmaxf(__ldg(r2 + x), __ldg(r2 + x + 1))));
                    if (!(nmx > vv)) {
                        unsigned u = __float_as_uint(vv);
                        unsigned ord = u ^ ((u >> 31) ? 0xFFFFFFFFu : 0x80000000u);
                        int pos = atomicAdd(&s_cnt, 1);
                        if (pos < 768)
                            stage[pos] = ((ull)(~ord) << 32) | (unsigned)(y*Ww + x);
                    }
                }
            }
        } else {
            // edge path (first/last row, first/last float4 of a row)
#pragma unroll
            for (int k = 0; k < 4; k++) {
                float vv = v[k];
                if (vv > cut) {
                    int x = xb + k;
                    float nmx = -3.4e38f;
                    if (x > 0)      nmx = fmaxf(nmx, (k > 0) ? v[k-1] : __ldg(r1 + x - 1));
                    if (x < Ww-1)   nmx = fmaxf(nmx, (k < 3) ? v[k+1] : __ldg(r1 + x + 1));
                    if (y > 0) {
                        const float* r0 = r1 - Ww;
                        nmx = fmaxf(nmx, __ldg(r0 + x));
                        if (x > 0)    nmx = fmaxf(nmx, __ldg(r0 + x - 1));
                        if (x < Ww-1) nmx = fmaxf(nmx, __ldg(r0 + x + 1));
                    }
                    if (y < Hh-1) {
                        const float* r2 = r1 + Ww;
                        nmx = fmaxf(nmx, __ldg(r2 + x));
                        if (x > 0)    nmx = fmaxf(nmx, __ldg(r2 + x - 1));
                        if (x < Ww-1) nmx = fmaxf(nmx, __ldg(r2 + x + 1));
                    }
                    if (!(nmx > vv)) {
                        unsigned u = __float_as_uint(vv);
                        unsigned ord = u ^ ((u >> 31) ? 0xFFFFFFFFu : 0x80000000u);
                        int pos = atomicAdd(&s_cnt, 1);
                        if (pos < 768)
                            stage[pos] = ((ull)(~ord) << 32) | (unsigned)(y*Ww + x);
                    }
                }
            }
        }
    }
    __syncthreads();
    int cnt = min(s_cnt, 768);
    if (tid == 0 && cnt) s_base = atomicAdd(&g_cnt[map], cnt);
    __syncthreads();
    if (cnt) {
        ull* dst = g_cand + (size_t)map*CAP;
        int bbase = s_base;
        for (int i = tid; i < cnt; i += 256)
            if (bbase + i < CAP) dst[bbase + i] = stage[i];
    }
}

// ---------------------------------------------------------------------------
// Kernel 4: exact top-K per map. 2-round 12-bit radix select -> compact
// -> rank-scatter (keys unique -> ranks are a permutation).
// ---------------------------------------------------------------------------
__global__ void __launch_bounds__(256) k_topk(float* __restrict__ out) {
    int map = blockIdx.x;
    int tid = threadIdx.x;
    int n = g_cnt[map]; if (n > CAP) n = CAP;
    const ull* cand = g_cand + (size_t)map*CAP;

    __shared__ int hist[4096];
    __shared__ int psum[256];
    __shared__ ull list[2048];
    __shared__ int sh_T, sh_C, nlist;

    unsigned thr24 = 0xFFFFFFu;
    if (n > Kk) {
        // ---- round 1: bits [63:52] ----
        for (int i = tid; i < 4096; i += 256) hist[i] = 0;
        __syncthreads();
#pragma unroll 4
        for (int i = tid; i < n; i += 256)
            atomicAdd(&hist[(int)(cand[i] >> 52)], 1);
        __syncthreads();
        int seg = 0;
        for (int j = 0; j < 16; j++) seg += hist[tid*16 + j];
        psum[tid] = seg;
        __syncthreads();
        if (tid == 0) { int run = 0; for (int t = 0; t < 256; t++) { int tmp = psum[t]; psum[t] = run; run += tmp; } }
        __syncthreads();
        if (psum[tid] < Kk && psum[tid] + seg >= Kk) {
            int c = psum[tid];
            for (int j = 0; j < 16; j++) {
                int h = hist[tid*16 + j];
                if (c + h >= Kk) { sh_T = tid*16 + j; sh_C = c; break; }
                c += h;
            }
        }
        __syncthreads();
        int T = sh_T, C0 = sh_C;
        // ---- round 2: bits [51:40] within bin T ----
        for (int i = tid; i < 4096; i += 256) hist[i] = 0;
        __syncthreads();
#pragma unroll 4
        for (int i = tid; i < n; i += 256) {
            ull key = cand[i];
            if ((int)(key >> 52) == T) atomicAdd(&hist[(int)((key >> 40) & 0xFFF)], 1);
        }
        __syncthreads();
        int need = Kk - C0;
        seg = 0;
        for (int j = 0; j < 16; j++) seg += hist[tid*16 + j];
        psum[tid] = seg;
        __syncthreads();
        if (tid == 0) { int run = 0; for (int t = 0; t < 256; t++) { int tmp = psum[t]; psum[t] = run; run += tmp; } }
        __syncthreads();
        if (psum[tid] < need && psum[tid] + seg >= need) {
            int c = psum[tid];
            for (int j = 0; j < 16; j++) {
                int h = hist[tid*16 + j];
                if (c + h >= need) { sh_T = tid*16 + j; break; }
                c += h;
            }
        }
        __syncthreads();
        thr24 = ((unsigned)T << 12) | (unsigned)sh_T;
    }

    if (tid == 0) nlist = 0;
    __syncthreads();
#pragma unroll 4
    for (int i = tid; i < n; i += 256) {
        ull key = cand[i];
        if ((unsigned)(key >> 40) <= thr24) {
            int p = atomicAdd(&nlist, 1);
            if (p < 2048) list[p] = key;
        }
    }
    __syncthreads();
    int M = min(nlist, 2048);
    float m = g_m[map];
    float invZ = 1.f / g_Z[map];

    // rank-scatter: element t's rank = #(keys < key_t); write slot 'rank'.
    for (int t = tid; t < M; t += 256) {
        ull k = list[t];
        int rank = 0;
        for (int j = 0; j < M; j++) rank += (list[j] < k);
        if (rank < Kk) {
            unsigned idx = (unsigned)(k & 0xFFFFFFFFu);
            int gx = idx & 511, gy = idx >> 9;
            unsigned ord = ~(unsigned)(k >> 32);
            unsigned u = (ord & 0x80000000u) ? (ord ^ 0x80000000u) : ~ord;
            float v = __uint_as_float(u);
            float sc = __expf(v - m) * invZ;
            int o = map*Kk + rank;
            out[OFF_SCORES + o]       = sc;
            out[OFF_COORDS + o*2]     = (float)gx;
            out[OFF_COORDS + o*2 + 1] = (float)gy;
            out[OFF_VALID  + o]       = 1.f;
            g_selx[o] = gx; g_sely[o] = gy; g_selv[o] = 1;
        }
    }
    // default-fill empty slots [M, Kk)
    if (tid >= M && tid < Kk) {
        int o = map*Kk + tid;
        out[OFF_SCORES + o]       = 0.f;
        out[OFF_COORDS + o*2]     = 0.f;
        out[OFF_COORDS + o*2 + 1] = 0.f;
        out[OFF_VALID  + o]       = 0.f;
        g_selx[o] = 0; g_sely[o] = 0; g_selv[o] = 0;
    }
}

// ---------------------------------------------------------------------------
// Kernel 5: KxK pair edges per (b,a). PAF gathered ONLY for valid pairs.
// ---------------------------------------------------------------------------
__global__ void __launch_bounds__(256) k_pairs(const float* __restrict__ paf,
                                               float* __restrict__ out) {
    int ba = blockIdx.x;                  // b*Aa + a
    int a  = ba % Aa;
    int b  = ba / Aa;
    int m1 = b*Ss + a, m2 = m1 + 1;
    __shared__ int x1[Kk], y1[Kk], v1[Kk], x2[Kk], y2[Kk], v2[Kk];
    int tid = threadIdx.x;
    if (tid < Kk) {
        x1[tid] = g_selx[m1*Kk + tid]; y1[tid] = g_sely[m1*Kk + tid]; v1[tid] = g_selv[m1*Kk + tid];
        x2[tid] = g_selx[m2*Kk + tid]; y2[tid] = g_sely[m2*Kk + tid]; v2[tid] = g_selv[m2*Kk + tid];
    }
    __syncthreads();
    const float* pafx = paf + (size_t)(ba*2)*HWs;
    const float* pafy = pafx + HWs;
    size_t eb = (size_t)ba * Kk * Kk;
    size_t ib = (size_t)ba * 2 * Kk * Kk;
    for (int idx = tid; idx < Kk*Kk; idx += 256) {
        int j2 = idx / Kk, j1 = idx - j2*Kk;
        float dx = (float)(x2[j2] - x1[j1]);
        float dy = (float)(y2[j2] - y1[j1]);
        float R = sqrtf(dx*dx + dy*dy);
        bool pv = (R < 20.0f) && v1[j1] && v2[j2];
        float li = 0.f;
        if (pv && R > 0.f) {
            float tvx = dx / R, tvy = dy / R;
            int px1 = x1[j1], py1 = y1[j1], px2 = x2[j2], py2 = y2[j2];
            float acc = 0.f;
#pragma unroll
            for (int t = 0; t < 10; t++) {
                int sx = (px1*(9 - t) + px2*t) / 9;
                int sy = (py1*(9 - t) + py2*t) / 9;
                int off = sy*Ww + sx;
                acc += tvx*__ldg(pafx + off) + tvy*__ldg(pafy + off);
            }
            li = acc * 0.1f;
        }
        out[OFF_EPAF + eb + idx] = li;
        out[OFF_ER   + eb + idx] = pv ? R : 0.f;
        out[OFF_PV   + eb + idx] = pv ? 1.f : 0.f;
        out[OFF_IP   + ib + idx]           = (float)(a*Kk + j1);
        out[OFF_IP   + ib + Kk*Kk + idx]   = (float)((a + 1)*Kk + j2);
    }
}

extern "C" void kernel_launch(void* const* d_in, const int* in_sizes, int n_in,
                              void* d_out, int out_size) {
    const float* pose = (const float*)d_in[0];
    const float* paf  = (const float*)d_in[1];
    float* out = (float*)d_out;
    k_reduce  <<<NMAPS*NPART, 256>>>(pose);
    k_finalize<<<1, 256>>>();
    k_nms     <<<dim3(HWs/1024, NMAPS), 256>>>(pose);
    k_topk    <<<NMAPS, 256>>>(out);
    k_pairs   <<<Bb*Aa, 256>>>(paf, out);
}

// round 6
// speedup vs baseline: 5.7678x; 1.3062x over previous
#include <cuda_runtime.h>
#include <cuda_fp16.h>
#include <cstdint>

#define Bb 8
#define Ss 25
#define Hh 512
#define Ww 512
#define Aa 20
#define Kk 100
#define NMAPS (Bb*Ss)        // 200
#define HWs (Hh*Ww)          // 262144
#define CAP 65536
#define NPART 16

#define OFF_SCORES 0
#define OFF_COORDS 20000
#define OFF_VALID  60000
#define OFF_EPAF   80000
#define OFF_ER     1680000
#define OFF_PV     3280000
#define OFF_IP     4880000

typedef unsigned long long ull;

__device__ float2 g_part[NMAPS*NPART];
__device__ float g_m[NMAPS];
__device__ float g_Z[NMAPS];
__device__ float g_cut[NMAPS];
__device__ int   g_cnt[NMAPS];
__device__ ull   g_cand[(size_t)NMAPS*CAP];
__device__ int g_selx[NMAPS*Kk];
__device__ int g_sely[NMAPS*Kk];
__device__ int g_selv[NMAPS*Kk];

__device__ __forceinline__ unsigned h2ex2(unsigned a) {
    unsigned r; asm("ex2.approx.f16x2 %0,%1;" : "=r"(r) : "r"(a)); return r;
}
__device__ __forceinline__ unsigned hadd2u(unsigned a, unsigned b) {
    unsigned r; asm("add.rn.f16x2 %0,%1,%2;" : "=r"(r) : "r"(a), "r"(b)); return r;
}
__device__ __forceinline__ unsigned pack_h2(float lo, float hi) {
    unsigned r; asm("cvt.rn.f16x2.f32 %0,%1,%2;" : "=r"(r) : "f"(hi), "f"(lo)); return r;
}

// ---------------------------------------------------------------------------
// Kernel 1: per-map partial (max, sum exp(v)) via ex2.approx.f16x2
// ---------------------------------------------------------------------------
__global__ void __launch_bounds__(256) k_reduce(const float* __restrict__ pose) {
    int blk = blockIdx.x;
    int map = blk / NPART, part = blk % NPART;
    const float4* p = (const float4*)(pose + (size_t)map*HWs + (size_t)part*(HWs/NPART));
    int tid = threadIdx.x;
    const float L2E = 1.4426950408889634f;
    float m = -3.4e38f;
    unsigned a0 = 0u, a1 = 0u;
#pragma unroll
    for (int c = 0; c < 16; c++) {
        float4 v = p[tid + 256*c];
        m = fmaxf(fmaxf(m, fmaxf(v.x, v.y)), fmaxf(v.z, v.w));
        unsigned y0 = pack_h2(v.x*L2E, v.y*L2E);
        unsigned y1 = pack_h2(v.z*L2E, v.w*L2E);
        a0 = hadd2u(a0, h2ex2(y0));
        a1 = hadd2u(a1, h2ex2(y1));
    }
    __half2 h0 = *(__half2*)&a0, h1 = *(__half2*)&a1;
    float2 f0 = __half22float2(h0), f1 = __half22float2(h1);
    float s = (f0.x + f0.y) + (f1.x + f1.y);
    for (int o = 16; o; o >>= 1) {
        m = fmaxf(m, __shfl_down_sync(0xFFFFFFFFu, m, o));
        s += __shfl_down_sync(0xFFFFFFFFu, s, o);
    }
    __shared__ float sm[8], ss[8];
    if ((tid & 31) == 0) { sm[tid>>5] = m; ss[tid>>5] = s; }
    __syncthreads();
    if (tid < 8) {
        m = sm[tid]; s = ss[tid];
        for (int o = 4; o; o >>= 1) {
            m = fmaxf(m, __shfl_down_sync(0xFFu, m, o));
            s += __shfl_down_sync(0xFFu, s, o);
        }
        if (tid == 0) g_part[blk] = make_float2(m, s);
    }
}

// ---------------------------------------------------------------------------
// Kernel 2: finalize m, Z, logit cutoff; reset counters
// ---------------------------------------------------------------------------
__global__ void k_finalize() {
    int map = threadIdx.x;
    if (map >= NMAPS) return;
    float m = -3.4e38f, S0 = 0.f;
#pragma unroll
    for (int i = 0; i < NPART; i++) {
        float2 p = g_part[map*NPART + i];
        m = fmaxf(m, p.x);
        S0 += p.y;
    }
    float Z = S0 * __expf(-m);
    g_m[map] = m; g_Z[map] = Z;
    float cut = m + fmaxf(__logf(Z * (2.0f / (float)HWs)), -4.6051702f);
    g_cut[map] = cut;
    g_cnt[map] = 0;
}

// ---------------------------------------------------------------------------
// Kernel 3: NMS via register-resident separable 3x3 max filter.
// Each warp: 128-column segment x 32-row strip. Rows stream through regs:
//   a = row[yc] raw, m01 = max(row[yc-1], row[yc]); load cur = row[yc+1];
//   vm = max(m01, cur); horizontal 3-max via shfl + in-register shifts.
// Candidate <=> (a > cut) && (a == hmax3x3). No divergent neighbor loads.
// ---------------------------------------------------------------------------
#define NMS_STAGE 6144
__global__ void __launch_bounds__(256) k_nms(const float* __restrict__ pose) {
    int map = blockIdx.y;
    int tid = threadIdx.x;
    int wrp = tid >> 5, lane = tid & 31;
    int wg = blockIdx.x * 8 + wrp;        // 64 warps per map
    int seg = wg & 3;                     // column segment [0,4)
    int strip = wg >> 2;                  // row strip [0,16)
    int C0 = seg * 128;
    int R0 = strip * 32;
    const float* pm = pose + (size_t)map*HWs;
    float cut = g_cut[map];

    __shared__ ull stage[NMS_STAGE];
    __shared__ int s_cnt, s_base;
    if (tid == 0) s_cnt = 0;
    __syncthreads();

    const float NEG = -3.4e38f;
    int xc = C0 + lane*4;
    // halo column: lane 0 -> C0-1, lane 31 -> C0+128
    bool hval = (lane == 0) ? (C0 > 0) : ((lane == 31) ? (C0 + 128 < Ww) : false);
    int hx = (lane == 0) ? (C0 - 1) : (C0 + 128);

    // init: a = row R0, m01 = max(row R0-1, a)
    float4 a, m01;
    {
        float4 t;
        if (R0 > 0) t = *(const float4*)(pm + (size_t)(R0-1)*Ww + xc);
        else t = make_float4(NEG, NEG, NEG, NEG);
        a = *(const float4*)(pm + (size_t)R0*Ww + xc);
        m01 = make_float4(fmaxf(t.x,a.x), fmaxf(t.y,a.y), fmaxf(t.z,a.z), fmaxf(t.w,a.w));
    }
    float haA = NEG, haM = NEG;
    if (hval) {
        float ht = (R0 > 0) ? __ldg(pm + (size_t)(R0-1)*Ww + hx) : NEG;
        haA = __ldg(pm + (size_t)R0*Ww + hx);
        haM = fmaxf(ht, haA);
    }

    for (int yc = R0; yc < R0 + 32; yc++) {
        int yn = yc + 1;
        float4 cur;
        float hcur = NEG;
        if (yn < Hh) {
            cur = *(const float4*)(pm + (size_t)yn*Ww + xc);
            if (hval) hcur = __ldg(pm + (size_t)yn*Ww + hx);
        } else {
            cur = make_float4(NEG, NEG, NEG, NEG);
        }
        float4 vm = make_float4(fmaxf(m01.x,cur.x), fmaxf(m01.y,cur.y),
                                fmaxf(m01.z,cur.z), fmaxf(m01.w,cur.w));
        float hvm = fmaxf(haM, hcur);
        float fromL = __shfl_up_sync(0xFFFFFFFFu, vm.w, 1);
        if (lane == 0) fromL = hvm;
        float fromR = __shfl_down_sync(0xFFFFFFFFu, vm.x, 1);
        if (lane == 31) fromR = hvm;
        float h0 = fmaxf(fromL, fmaxf(vm.x, vm.y));
        float h1 = fmaxf(vm.x,  fmaxf(vm.y, vm.z));
        float h2 = fmaxf(vm.y,  fmaxf(vm.z, vm.w));
        float h3 = fmaxf(vm.z,  fmaxf(vm.w, fromR));

        float av[4] = {a.x, a.y, a.z, a.w};
        float hv[4] = {h0, h1, h2, h3};
#pragma unroll
        for (int k = 0; k < 4; k++) {
            float vv = av[k];
            if (vv > cut && vv == hv[k]) {
                unsigned u = __float_as_uint(vv);
                unsigned ord = u ^ ((u >> 31) ? 0xFFFFFFFFu : 0x80000000u);
                int pos = atomicAdd(&s_cnt, 1);
                if (pos < NMS_STAGE)
                    stage[pos] = ((ull)(~ord) << 32) | (unsigned)(yc*Ww + xc + k);
            }
        }
        m01 = make_float4(fmaxf(a.x,cur.x), fmaxf(a.y,cur.y),
                          fmaxf(a.z,cur.z), fmaxf(a.w,cur.w));
        a = cur;
        haM = fmaxf(haA, hcur); haA = hcur;
    }
    __syncthreads();
    int cnt = min(s_cnt, NMS_STAGE);
    if (tid == 0 && cnt) s_base = atomicAdd(&g_cnt[map], cnt);
    __syncthreads();
    if (cnt) {
        ull* dst = g_cand + (size_t)map*CAP;
        int bbase = s_base;
        for (int i = tid; i < cnt; i += 256)
            if (bbase + i < CAP) dst[bbase + i] = stage[i];
    }
}

// ---------------------------------------------------------------------------
// Kernel 4: exact top-K. Radix round 1 (bits [63:52]); if the threshold-bin
// prefix fits in the 2048-entry list (virtually always), compact directly —
// otherwise refine with round 2. Then rank-scatter.
// ---------------------------------------------------------------------------
__global__ void __launch_bounds__(512) k_topk(float* __restrict__ out) {
    int map = blockIdx.x;
    int tid = threadIdx.x;
    int n = g_cnt[map]; if (n > CAP) n = CAP;
    const ull* cand = g_cand + (size_t)map*CAP;

    __shared__ int hist[4096];
    __shared__ int psum[256];
    __shared__ ull list[2048];
    __shared__ int sh_T, sh_C, sh_H, nlist;
    __shared__ int sh_mode;   // 0: take all; 1: 12-bit thr; 2: 24-bit thr

    unsigned thr24 = 0;
    int T12 = 0;
    if (tid == 0) sh_mode = 0;

    if (n > Kk) {
        // ---- round 1: bits [63:52] ----
        for (int i = tid; i < 4096; i += 512) hist[i] = 0;
        __syncthreads();
#pragma unroll 8
        for (int i = tid; i < n; i += 512)
            atomicAdd(&hist[(int)(__ldg(cand + i) >> 52)], 1);
        __syncthreads();
        if (tid < 256) {
            int seg = 0;
            for (int j = 0; j < 16; j++) seg += hist[tid*16 + j];
            psum[tid] = seg;
        }
        __syncthreads();
        if (tid == 0) { int run = 0; for (int t = 0; t < 256; t++) { int tmp = psum[t]; psum[t] = run; run += tmp; } }
        __syncthreads();
        if (tid < 256) {
            int c = psum[tid];
            int hi = 0;
            for (int j = 0; j < 16; j++) hi += hist[tid*16 + j];
            if (c < Kk && c + hi >= Kk) {
                int cc = c;
                for (int j = 0; j < 16; j++) {
                    int h = hist[tid*16 + j];
                    if (cc + h >= Kk) { sh_T = tid*16 + j; sh_C = cc; sh_H = h; break; }
                    cc += h;
                }
            }
        }
        __syncthreads();
        int T = sh_T, C0 = sh_C, HT = sh_H;
        if (C0 + HT <= 2048) {
            if (tid == 0) sh_mode = 1;
            T12 = T;
        } else {
            // ---- round 2: bits [51:40] within bin T (rare fallback) ----
            __syncthreads();
            for (int i = tid; i < 4096; i += 512) hist[i] = 0;
            __syncthreads();
            for (int i = tid; i < n; i += 512) {
                ull key = __ldg(cand + i);
                if ((int)(key >> 52) == T) atomicAdd(&hist[(int)((key >> 40) & 0xFFF)], 1);
            }
            __syncthreads();
            int need = Kk - C0;
            if (tid < 256) {
                int seg = 0;
                for (int j = 0; j < 16; j++) seg += hist[tid*16 + j];
                psum[tid] = seg;
            }
            __syncthreads();
            if (tid == 0) { int run = 0; for (int t = 0; t < 256; t++) { int tmp = psum[t]; psum[t] = run; run += tmp; } }
            __syncthreads();
            if (tid < 256) {
                int c = psum[tid];
                int hi = 0;
                for (int j = 0; j < 16; j++) hi += hist[tid*16 + j];
                if (c < need && c + hi >= need) {
                    int cc = c;
                    for (int j = 0; j < 16; j++) {
                        int h = hist[tid*16 + j];
                        if (cc + h >= need) { sh_T = tid*16 + j; break; }
                        cc += h;
                    }
                }
            }
            if (tid == 0) sh_mode = 2;
            __syncthreads();
            thr24 = ((unsigned)T << 12) | (unsigned)sh_T;
            T12 = T;
        }
    }
    __syncthreads();
    int mode = sh_mode;

    if (tid == 0) nlist = 0;
    __syncthreads();
#pragma unroll 4
    for (int i = tid; i < n; i += 512) {
        ull key = __ldg(cand + i);
        bool keep;
        if (mode == 0)      keep = true;
        else if (mode == 1) keep = ((int)(key >> 52) <= T12);
        else                keep = ((unsigned)(key >> 40) <= thr24);
        if (keep) {
            int p = atomicAdd(&nlist, 1);
            if (p < 2048) list[p] = key;
        }
    }
    __syncthreads();
    int M = min(nlist, 2048);
    float m = g_m[map];
    float invZ = 1.f / g_Z[map];

    // rank-scatter: rank = #(keys < key); write slot 'rank' directly.
    for (int t = tid; t < M; t += 512) {
        ull k = list[t];
        int rank = 0;
        for (int j = 0; j < M; j++) rank += (list[j] < k);
        if (rank < Kk) {
            unsigned idx = (unsigned)(k & 0xFFFFFFFFu);
            int gx = idx & 511, gy = idx >> 9;
            unsigned ord = ~(unsigned)(k >> 32);
            unsigned u = (ord & 0x80000000u) ? (ord ^ 0x80000000u) : ~ord;
            float v = __uint_as_float(u);
            float sc = __expf(v - m) * invZ;
            int o = map*Kk + rank;
            out[OFF_SCORES + o]       = sc;
            out[OFF_COORDS + o*2]     = (float)gx;
            out[OFF_COORDS + o*2 + 1] = (float)gy;
            out[OFF_VALID  + o]       = 1.f;
            g_selx[o] = gx; g_sely[o] = gy; g_selv[o] = 1;
        }
    }
    if (tid >= M && tid < Kk) {
        int o = map*Kk + tid;
        out[OFF_SCORES + o]       = 0.f;
        out[OFF_COORDS + o*2]     = 0.f;
        out[OFF_COORDS + o*2 + 1] = 0.f;
        out[OFF_VALID  + o]       = 0.f;
        g_selx[o] = 0; g_sely[o] = 0; g_selv[o] = 0;
    }
}

// ---------------------------------------------------------------------------
// Kernel 5: KxK pair edges per (b,a). PAF gathered only for valid pairs.
// ---------------------------------------------------------------------------
__global__ void __launch_bounds__(256) k_pairs(const float* __restrict__ paf,
                                               float* __restrict__ out) {
    int ba = blockIdx.x;
    int a  = ba % Aa;
    int b  = ba / Aa;
    int m1 = b*Ss + a, m2 = m1 + 1;
    __shared__ int x1[Kk], y1[Kk], v1[Kk], x2[Kk], y2[Kk], v2[Kk];
    int tid = threadIdx.x;
    if (tid < Kk) {
        x1[tid] = g_selx[m1*Kk + tid]; y1[tid] = g_sely[m1*Kk + tid]; v1[tid] = g_selv[m1*Kk + tid];
        x2[tid] = g_selx[m2*Kk + tid]; y2[tid] = g_sely[m2*Kk + tid]; v2[tid] = g_selv[m2*Kk + tid];
    }
    __syncthreads();
    const float* pafx = paf + (size_t)(ba*2)*HWs;
    const float* pafy = pafx + HWs;
    size_t eb = (size_t)ba * Kk * Kk;
    size_t ib = (size_t)ba * 2 * Kk * Kk;
    for (int idx = tid; idx < Kk*Kk; idx += 256) {
        int j2 = idx / Kk, j1 = idx - j2*Kk;
        float dx = (float)(x2[j2] - x1[j1]);
        float dy = (float)(y2[j2] - y1[j1]);
        float R = sqrtf(dx*dx + dy*dy);
        bool pv = (R < 20.0f) && v1[j1] && v2[j2];
        float li = 0.f;
        if (pv && R > 0.f) {
            float tvx = dx / R, tvy = dy / R;
            int px1 = x1[j1], py1 = y1[j1], px2 = x2[j2], py2 = y2[j2];
            float acc = 0.f;
#pragma unroll
            for (int t = 0; t < 10; t++) {
                int sx = (px1*(9 - t) + px2*t) / 9;
                int sy = (py1*(9 - t) + py2*t) / 9;
                int off = sy*Ww + sx;
                acc += tvx*__ldg(pafx + off) + tvy*__ldg(pafy + off);
            }
            li = acc * 0.1f;
        }
        out[OFF_EPAF + eb + idx] = li;
        out[OFF_ER   + eb + idx] = pv ? R : 0.f;
        out[OFF_PV   + eb + idx] = pv ? 1.f : 0.f;
        out[OFF_IP   + ib + idx]           = (float)(a*Kk + j1);
        out[OFF_IP   + ib + Kk*Kk + idx]   = (float)((a + 1)*Kk + j2);
    }
}

extern "C" void kernel_launch(void* const* d_in, const int* in_sizes, int n_in,
                              void* d_out, int out_size) {
    const float* pose = (const float*)d_in[0];
    const float* paf  = (const float*)d_in[1];
    float* out = (float*)d_out;
    k_reduce  <<<NMAPS*NPART, 256>>>(pose);
    k_finalize<<<1, 256>>>();
    k_nms     <<<dim3(8, NMAPS), 256>>>(pose);
    k_topk    <<<NMAPS, 512>>>(out);
    k_pairs   <<<Bb*Aa, 256>>>(paf, out);
}

// round 7
// speedup vs baseline: 5.8430x; 1.0130x over previous
#include <cuda_runtime.h>
#include <cuda_fp16.h>
#include <cstdint>

#define Bb 8
#define Ss 25
#define Hh 512
#define Ww 512
#define Aa 20
#define Kk 100
#define NMAPS (Bb*Ss)        // 200
#define HWs (Hh*Ww)          // 262144
#define CAP 65536
#define BSEG 8192            // per-block candidate segment (8 blocks/map)
#define NSTAGE 6144

#define OFF_SCORES 0
#define OFF_COORDS 20000
#define OFF_VALID  60000
#define OFF_EPAF   80000
#define OFF_ER     1680000
#define OFF_PV     3280000
#define OFF_IP     4880000

typedef unsigned long long ull;

__device__ float2 g_part[NMAPS*8];
__device__ float g_m[NMAPS];
__device__ float g_Z[NMAPS];
__device__ ull   g_cutkey[NMAPS];
__device__ int   g_bcnt[NMAPS*8];
__device__ ull   g_cand[(size_t)NMAPS*CAP];
__device__ int g_selx[NMAPS*Kk];
__device__ int g_sely[NMAPS*Kk];
__device__ int g_selv[NMAPS*Kk];

__device__ __forceinline__ unsigned h2ex2(unsigned a) {
    unsigned r; asm("ex2.approx.f16x2 %0,%1;" : "=r"(r) : "r"(a)); return r;
}
__device__ __forceinline__ unsigned hadd2u(unsigned a, unsigned b) {
    unsigned r; asm("add.rn.f16x2 %0,%1,%2;" : "=r"(r) : "r"(a), "r"(b)); return r;
}
__device__ __forceinline__ unsigned pack_h2(float lo, float hi) {
    unsigned r; asm("cvt.rn.f16x2.f32 %0,%1,%2;" : "=r"(r) : "f"(hi), "f"(lo)); return r;
}

// ---------------------------------------------------------------------------
// Kernel 1 (fused): ONE pose_map pass per map does:
//   - per-strip (max, sum exp) via ex2.approx.f16x2 (folded to f32 every 8 rows)
//   - register-streaming separable 3x3 max stencil; pushes ALL local maxima
//     (threshold applied later in k_topk once global cut is known)
// Per-block candidate segments + plain count stores: no global atomics,
// no counter reset kernel needed.
// ---------------------------------------------------------------------------
__global__ void __launch_bounds__(256) k_fused(const float* __restrict__ pose) {
    int map = blockIdx.y;
    int tid = threadIdx.x;
    int wrp = tid >> 5, lane = tid & 31;
    int wg = blockIdx.x * 8 + wrp;        // 64 warps per map
    int seg = wg & 3;                     // column segment [0,4)
    int strip = wg >> 2;                  // row strip [0,16)
    int C0 = seg * 128;
    int R0 = strip * 32;
    const float* pm = pose + (size_t)map*HWs;

    __shared__ ull stage[NSTAGE];
    __shared__ int s_cnt;
    __shared__ float sm[8], ss[8];
    if (tid == 0) s_cnt = 0;
    __syncthreads();

    const float NEG = -3.4e38f;
    const float L2E = 1.4426950408889634f;
    int xc = C0 + lane*4;
    bool hval = (lane == 0) ? (C0 > 0) : ((lane == 31) ? (C0 + 128 < Ww) : false);
    int hx = (lane == 0) ? (C0 - 1) : (C0 + 128);

    float4 a, m01;
    {
        float4 t;
        if (R0 > 0) t = *(const float4*)(pm + (size_t)(R0-1)*Ww + xc);
        else t = make_float4(NEG, NEG, NEG, NEG);
        a = *(const float4*)(pm + (size_t)R0*Ww + xc);
        m01 = make_float4(fmaxf(t.x,a.x), fmaxf(t.y,a.y), fmaxf(t.z,a.z), fmaxf(t.w,a.w));
    }
    float haA = NEG, haM = NEG;
    if (hval) {
        float ht = (R0 > 0) ? __ldg(pm + (size_t)(R0-1)*Ww + hx) : NEG;
        haA = __ldg(pm + (size_t)R0*Ww + hx);
        haM = fmaxf(ht, haA);
    }

    float mx = NEG;
    float s = 0.f;
    for (int c8 = 0; c8 < 4; c8++) {
        unsigned acc0 = 0u, acc1 = 0u;    // f16x2, only 8 adds before f32 fold
#pragma unroll
        for (int r = 0; r < 8; r++) {
            int yc = R0 + c8*8 + r;
            // center row 'a' is owned: accumulate max + exp
            mx = fmaxf(fmaxf(mx, fmaxf(a.x,a.y)), fmaxf(a.z,a.w));
            acc0 = hadd2u(acc0, h2ex2(pack_h2(a.x*L2E, a.y*L2E)));
            acc1 = hadd2u(acc1, h2ex2(pack_h2(a.z*L2E, a.w*L2E)));
            // 3x3 stencil
            int yn = yc + 1;
            float4 cur; float hcur = NEG;
            if (yn < Hh) {
                cur = *(const float4*)(pm + (size_t)yn*Ww + xc);
                if (hval) hcur = __ldg(pm + (size_t)yn*Ww + hx);
            } else {
                cur = make_float4(NEG, NEG, NEG, NEG);
            }
            float4 vm = make_float4(fmaxf(m01.x,cur.x), fmaxf(m01.y,cur.y),
                                    fmaxf(m01.z,cur.z), fmaxf(m01.w,cur.w));
            float hvm = fmaxf(haM, hcur);
            float fromL = __shfl_up_sync(0xFFFFFFFFu, vm.w, 1);
            if (lane == 0) fromL = hvm;
            float fromR = __shfl_down_sync(0xFFFFFFFFu, vm.x, 1);
            if (lane == 31) fromR = hvm;
            float h0 = fmaxf(fromL, fmaxf(vm.x, vm.y));
            float h1 = fmaxf(vm.x,  fmaxf(vm.y, vm.z));
            float h2 = fmaxf(vm.y,  fmaxf(vm.z, vm.w));
            float h3 = fmaxf(vm.z,  fmaxf(vm.w, fromR));
            float av[4] = {a.x, a.y, a.z, a.w};
            float hv[4] = {h0, h1, h2, h3};
#pragma unroll
            for (int k = 0; k < 4; k++) {
                float vv = av[k];
                if (vv == hv[k]) {        // 3x3 local max (ties pass, as in ref)
                    unsigned u = __float_as_uint(vv);
                    unsigned ord = u ^ ((u >> 31) ? 0xFFFFFFFFu : 0x80000000u);
                    int pos = atomicAdd(&s_cnt, 1);
                    if (pos < NSTAGE)
                        stage[pos] = ((ull)(~ord) << 32) | (unsigned)(yc*Ww + xc + k);
                }
            }
            m01 = make_float4(fmaxf(a.x,cur.x), fmaxf(a.y,cur.y),
                              fmaxf(a.z,cur.z), fmaxf(a.w,cur.w));
            a = cur;
            haM = fmaxf(haA, hcur); haA = hcur;
        }
        __half2 hh0 = *(__half2*)&acc0, hh1 = *(__half2*)&acc1;
        float2 f0 = __half22float2(hh0), f1 = __half22float2(hh1);
        s += (f0.x + f0.y) + (f1.x + f1.y);
    }

    // block reduce (max, sum)
    for (int o = 16; o; o >>= 1) {
        mx = fmaxf(mx, __shfl_down_sync(0xFFFFFFFFu, mx, o));
        s += __shfl_down_sync(0xFFFFFFFFu, s, o);
    }
    if (lane == 0) { sm[wrp] = mx; ss[wrp] = s; }
    __syncthreads();
    if (tid < 8) {
        mx = sm[tid]; s = ss[tid];
        for (int o = 4; o; o >>= 1) {
            mx = fmaxf(mx, __shfl_down_sync(0xFFu, mx, o));
            s += __shfl_down_sync(0xFFu, s, o);
        }
        if (tid == 0) g_part[map*8 + blockIdx.x] = make_float2(mx, s);
    }

    // write candidate segment (per-block region, no global atomic)
    int cnt = min(s_cnt, NSTAGE);
    if (tid == 0) g_bcnt[map*8 + blockIdx.x] = cnt;
    ull* dst = g_cand + (size_t)map*CAP + (size_t)blockIdx.x*BSEG;
    for (int i = tid; i < cnt; i += 256) dst[i] = stage[i];
}

// ---------------------------------------------------------------------------
// Kernel 2: finalize m, Z, logit cutoff -> key-space threshold
// ---------------------------------------------------------------------------
__global__ void k_finalize() {
    int map = threadIdx.x;
    if (map >= NMAPS) return;
    float m = -3.4e38f, S0 = 0.f;
#pragma unroll
    for (int i = 0; i < 8; i++) {
        float2 p = g_part[map*8 + i];
        m = fmaxf(m, p.x);
        S0 += p.y;
    }
    float Z = S0 * __expf(-m);
    g_m[map] = m; g_Z[map] = Z;
    float cut = m + fmaxf(__logf(Z * (2.0f / (float)HWs)), -4.6051702f);
    unsigned u = __float_as_uint(cut);
    unsigned ord = u ^ ((u >> 31) ? 0xFFFFFFFFu : 0x80000000u);
    // key < cutkey  <=>  value > cut (strict; low 32 index bits < 2^32)
    g_cutkey[map] = ((ull)(~ord)) << 32;
}

// ---------------------------------------------------------------------------
// Kernel 3: exact top-K over cut-filtered candidates. Radix round 1
// (bits[63:52]) with round-2 fallback, compact, rank-scatter.
// ---------------------------------------------------------------------------
__global__ void __launch_bounds__(512) k_topk(float* __restrict__ out) {
    int map = blockIdx.x;
    int tid = threadIdx.x;
    const ull* cand = g_cand + (size_t)map*CAP;
    ull cutkey = g_cutkey[map];

    __shared__ int bcnt[8];
    __shared__ int hist[4096];
    __shared__ int psum[256];
    __shared__ ull list[2048];
    __shared__ int sh_T, sh_C, sh_H, nlist, sh_tot;
    __shared__ int sh_mode;   // 0: take all passing; 1: 12-bit thr; 2: 24-bit thr

    if (tid < 8) bcnt[tid] = min(g_bcnt[map*8 + tid], NSTAGE);
    for (int i = tid; i < 4096; i += 512) hist[i] = 0;
    if (tid == 0) { sh_mode = 0; nlist = 0; }
    __syncthreads();

    // histogram over passing keys
    for (int sgi = 0; sgi < 8; sgi++) {
        int ns = bcnt[sgi];
        const ull* sp = cand + sgi*BSEG;
        for (int i = tid; i < ns; i += 512) {
            ull key = __ldg(sp + i);
            if (key < cutkey) atomicAdd(&hist[(int)(key >> 52)], 1);
        }
    }
    __syncthreads();
    if (tid < 256) {
        int sg = 0;
        for (int j = 0; j < 16; j++) sg += hist[tid*16 + j];
        psum[tid] = sg;
    }
    __syncthreads();
    if (tid == 0) {
        int run = 0;
        for (int t = 0; t < 256; t++) { int tmp = psum[t]; psum[t] = run; run += tmp; }
        sh_tot = run;
    }
    __syncthreads();
    int ntot = sh_tot;

    unsigned thr24 = 0;
    int T12 = 0;
    if (ntot > Kk) {
        if (tid < 256) {
            int c = psum[tid];
            int hi = 0;
            for (int j = 0; j < 16; j++) hi += hist[tid*16 + j];
            if (c < Kk && c + hi >= Kk) {
                int cc = c;
                for (int j = 0; j < 16; j++) {
                    int h = hist[tid*16 + j];
                    if (cc + h >= Kk) { sh_T = tid*16 + j; sh_C = cc; sh_H = h; break; }
                    cc += h;
                }
            }
        }
        __syncthreads();
        int T = sh_T, C0 = sh_C, HT = sh_H;
        if (C0 + HT <= 2048) {
            if (tid == 0) sh_mode = 1;
            T12 = T;
        } else {
            // round 2: bits [51:40] within bin T (rare)
            __syncthreads();
            for (int i = tid; i < 4096; i += 512) hist[i] = 0;
            __syncthreads();
            for (int sgi = 0; sgi < 8; sgi++) {
                int ns = bcnt[sgi];
                const ull* sp = cand + sgi*BSEG;
                for (int i = tid; i < ns; i += 512) {
                    ull key = __ldg(sp + i);
                    if (key < cutkey && (int)(key >> 52) == T)
                        atomicAdd(&hist[(int)((key >> 40) & 0xFFF)], 1);
                }
            }
            __syncthreads();
            int need = Kk - C0;
            if (tid < 256) {
                int sg = 0;
                for (int j = 0; j < 16; j++) sg += hist[tid*16 + j];
                psum[tid] = sg;
            }
            __syncthreads();
            if (tid == 0) { int run = 0; for (int t = 0; t < 256; t++) { int tmp = psum[t]; psum[t] = run; run += tmp; } }
            __syncthreads();
            if (tid < 256) {
                int c = psum[tid];
                int hi = 0;
                for (int j = 0; j < 16; j++) hi += hist[tid*16 + j];
                if (c < need && c + hi >= need) {
                    int cc = c;
                    for (int j = 0; j < 16; j++) {
                        int h = hist[tid*16 + j];
                        if (cc + h >= need) { sh_T = tid*16 + j; break; }
                        cc += h;
                    }
                }
            }
            if (tid == 0) sh_mode = 2;
            __syncthreads();
            thr24 = ((unsigned)T << 12) | (unsigned)sh_T;
            T12 = T;
        }
    }
    __syncthreads();
    int mode = sh_mode;

    // compact passing keys under the radix threshold
    for (int sgi = 0; sgi < 8; sgi++) {
        int ns = bcnt[sgi];
        const ull* sp = cand + sgi*BSEG;
        for (int i = tid; i < ns; i += 512) {
            ull key = __ldg(sp + i);
            if (key >= cutkey) continue;
            bool keep;
            if (mode == 0)      keep = true;
            else if (mode == 1) keep = ((int)(key >> 52) <= T12);
            else                keep = ((unsigned)(key >> 40) <= thr24);
            if (keep) {
                int p = atomicAdd(&nlist, 1);
                if (p < 2048) list[p] = key;
            }
        }
    }
    __syncthreads();
    int M = min(nlist, 2048);
    float m = g_m[map];
    float invZ = 1.f / g_Z[map];

    // rank-scatter: rank = #(keys < key); write slot 'rank' directly.
    for (int t = tid; t < M; t += 512) {
        ull k = list[t];
        int rank = 0;
        for (int j = 0; j < M; j++) rank += (list[j] < k);
        if (rank < Kk) {
            unsigned idx = (unsigned)(k & 0xFFFFFFFFu);
            int gx = idx & 511, gy = idx >> 9;
            unsigned ord = ~(unsigned)(k >> 32);
            unsigned u = (ord & 0x80000000u) ? (ord ^ 0x80000000u) : ~ord;
            float v = __uint_as_float(u);
            float sc = __expf(v - m) * invZ;
            int o = map*Kk + rank;
            out[OFF_SCORES + o]       = sc;
            out[OFF_COORDS + o*2]     = (float)gx;
            out[OFF_COORDS + o*2 + 1] = (float)gy;
            out[OFF_VALID  + o]       = 1.f;
            g_selx[o] = gx; g_sely[o] = gy; g_selv[o] = 1;
        }
    }
    if (tid >= M && tid < Kk) {
        int o = map*Kk + tid;
        out[OFF_SCORES + o]       = 0.f;
        out[OFF_COORDS + o*2]     = 0.f;
        out[OFF_COORDS + o*2 + 1] = 0.f;
        out[OFF_VALID  + o]       = 0.f;
        g_selx[o] = 0; g_sely[o] = 0; g_selv[o] = 0;
    }
}

// ---------------------------------------------------------------------------
// Kernel 4: KxK pair edges per (b,a). PAF gathered only for valid pairs.
// ---------------------------------------------------------------------------
__global__ void __launch_bounds__(256) k_pairs(const float* __restrict__ paf,
                                               float* __restrict__ out) {
    int ba = blockIdx.x;
    int a  = ba % Aa;
    int b  = ba / Aa;
    int m1 = b*Ss + a, m2 = m1 + 1;
    __shared__ int x1[Kk], y1[Kk], v1[Kk], x2[Kk], y2[Kk], v2[Kk];
    int tid = threadIdx.x;
    if (tid < Kk) {
        x1[tid] = g_selx[m1*Kk + tid]; y1[tid] = g_sely[m1*Kk + tid]; v1[tid] = g_selv[m1*Kk + tid];
        x2[tid] = g_selx[m2*Kk + tid]; y2[tid] = g_sely[m2*Kk + tid]; v2[tid] = g_selv[m2*Kk + tid];
    }
    __syncthreads();
    const float* pafx = paf + (size_t)(ba*2)*HWs;
    const float* pafy = pafx + HWs;
    size_t eb = (size_t)ba * Kk * Kk;
    size_t ib = (size_t)ba * 2 * Kk * Kk;
    for (int idx = tid; idx < Kk*Kk; idx += 256) {
        int j2 = idx / Kk, j1 = idx - j2*Kk;
        float dx = (float)(x2[j2] - x1[j1]);
        float dy = (float)(y2[j2] - y1[j1]);
        float R = sqrtf(dx*dx + dy*dy);
        bool pv = (R < 20.0f) && v1[j1] && v2[j2];
        float li = 0.f;
        if (pv && R > 0.f) {
            float tvx = dx / R, tvy = dy / R;
            int px1 = x1[j1], py1 = y1[j1], px2 = x2[j2], py2 = y2[j2];
            float acc = 0.f;
#pragma unroll
            for (int t = 0; t < 10; t++) {
                int sx = (px1*(9 - t) + px2*t) / 9;
                int sy = (py1*(9 - t) + py2*t) / 9;
                int off = sy*Ww + sx;
                acc += tvx*__ldg(pafx + off) + tvy*__ldg(pafy + off);
            }
            li = acc * 0.1f;
        }
        out[OFF_EPAF + eb + idx] = li;
        out[OFF_ER   + eb + idx] = pv ? R : 0.f;
        out[OFF_PV   + eb + idx] = pv ? 1.f : 0.f;
        out[OFF_IP   + ib + idx]           = (float)(a*Kk + j1);
        out[OFF_IP   + ib + Kk*Kk + idx]   = (float)((a + 1)*Kk + j2);
    }
}

extern "C" void kernel_launch(void* const* d_in, const int* in_sizes, int n_in,
                              void* d_out, int out_size) {
    const float* pose = (const float*)d_in[0];
    const float* paf  = (const float*)d_in[1];
    float* out = (float*)d_out;
    k_fused   <<<dim3(8, NMAPS), 256>>>(pose);
    k_finalize<<<1, 256>>>();
    k_topk    <<<NMAPS, 512>>>(out);
    k_pairs   <<<Bb*Aa, 256>>>(paf, out);
}

// round 8
// speedup vs baseline: 6.4690x; 1.1071x over previous
#include <cuda_runtime.h>
#include <cuda_fp16.h>
#include <cstdint>

#define Bb 8
#define Ss 25
#define Hh 512
#define Ww 512
#define Aa 20
#define Kk 100
#define NMAPS (Bb*Ss)        // 200
#define HWs (Hh*Ww)          // 262144
#define CAP 65536            // 64 warps/map * 1024-slot warp segments
#define WSEG 1024

#define OFF_SCORES 0
#define OFF_COORDS 20000
#define OFF_VALID  60000
#define OFF_EPAF   80000
#define OFF_ER     1680000
#define OFF_PV     3280000
#define OFF_IP     4880000

typedef unsigned long long ull;

__device__ float2 g_part[NMAPS*8];
__device__ float g_m[NMAPS];
__device__ float g_Z[NMAPS];
__device__ ull   g_cutkey[NMAPS];
__device__ int   g_bcnt[NMAPS*64];
__device__ ull   g_cand[(size_t)NMAPS*CAP];
__device__ int g_selx[NMAPS*Kk];
__device__ int g_sely[NMAPS*Kk];
__device__ int g_selv[NMAPS*Kk];

__device__ __forceinline__ unsigned h2ex2(unsigned a) {
    unsigned r; asm("ex2.approx.f16x2 %0,%1;" : "=r"(r) : "r"(a)); return r;
}
__device__ __forceinline__ unsigned hadd2u(unsigned a, unsigned b) {
    unsigned r; asm("add.rn.f16x2 %0,%1,%2;" : "=r"(r) : "r"(a), "r"(b)); return r;
}
__device__ __forceinline__ unsigned pack_h2(float lo, float hi) {
    unsigned r; asm("cvt.rn.f16x2.f32 %0,%1,%2;" : "=r"(r) : "f"(hi), "f"(lo)); return r;
}

// ---------------------------------------------------------------------------
// Kernel 1 (fused): ONE pose_map pass per map:
//   - (max, sum exp) via ex2.approx.f16x2 (f32 fold every 8 rows)
//   - register-streaming separable 3x3 max stencil; local maxima pushed via
//     warp-ballot aggregation into warp-private 1024-slot gmem segments.
//     (<= ceil(128/2)*ceil(32/2) = 1024 maxima possible per strip.)
// No smem staging, no atomics of any kind.
// ---------------------------------------------------------------------------
__global__ void __launch_bounds__(256) k_fused(const float* __restrict__ pose) {
    int map = blockIdx.y;
    int tid = threadIdx.x;
    int wrp = tid >> 5, lane = tid & 31;
    int wg = blockIdx.x * 8 + wrp;        // 64 warps per map
    int seg = wg & 3;                     // column segment [0,4)
    int strip = wg >> 2;                  // row strip [0,16)
    int C0 = seg * 128;
    int R0 = strip * 32;
    const float* pm = pose + (size_t)map*HWs;

    __shared__ float sm[8], ss[8];

    const float NEG = -3.4e38f;
    const float L2E = 1.4426950408889634f;
    int xc = C0 + lane*4;
    bool hval = (lane == 0) ? (C0 > 0) : ((lane == 31) ? (C0 + 128 < Ww) : false);
    int hx = (lane == 0) ? (C0 - 1) : (C0 + 128);

    ull* wdst = g_cand + (size_t)map*CAP + (size_t)wg*WSEG;
    int wcnt = 0;

    float4 a, m01;
    {
        float4 t;
        if (R0 > 0) t = *(const float4*)(pm + (size_t)(R0-1)*Ww + xc);
        else t = make_float4(NEG, NEG, NEG, NEG);
        a = *(const float4*)(pm + (size_t)R0*Ww + xc);
        m01 = make_float4(fmaxf(t.x,a.x), fmaxf(t.y,a.y), fmaxf(t.z,a.z), fmaxf(t.w,a.w));
    }
    float haA = NEG, haM = NEG;
    if (hval) {
        float ht = (R0 > 0) ? __ldg(pm + (size_t)(R0-1)*Ww + hx) : NEG;
        haA = __ldg(pm + (size_t)R0*Ww + hx);
        haM = fmaxf(ht, haA);
    }

    float mx = NEG;
    float s = 0.f;
    for (int c8 = 0; c8 < 4; c8++) {
        unsigned acc0 = 0u, acc1 = 0u;    // f16x2 accumulators, 8 adds max
#pragma unroll
        for (int r = 0; r < 8; r++) {
            int yc = R0 + c8*8 + r;
            mx = fmaxf(fmaxf(mx, fmaxf(a.x,a.y)), fmaxf(a.z,a.w));
            acc0 = hadd2u(acc0, h2ex2(pack_h2(a.x*L2E, a.y*L2E)));
            acc1 = hadd2u(acc1, h2ex2(pack_h2(a.z*L2E, a.w*L2E)));
            int yn = yc + 1;
            float4 cur; float hcur = NEG;
            if (yn < Hh) {
                cur = *(const float4*)(pm + (size_t)yn*Ww + xc);
                if (hval) hcur = __ldg(pm + (size_t)yn*Ww + hx);
            } else {
                cur = make_float4(NEG, NEG, NEG, NEG);
            }
            float4 vm = make_float4(fmaxf(m01.x,cur.x), fmaxf(m01.y,cur.y),
                                    fmaxf(m01.z,cur.z), fmaxf(m01.w,cur.w));
            float hvm = fmaxf(haM, hcur);
            float fromL = __shfl_up_sync(0xFFFFFFFFu, vm.w, 1);
            if (lane == 0) fromL = hvm;
            float fromR = __shfl_down_sync(0xFFFFFFFFu, vm.x, 1);
            if (lane == 31) fromR = hvm;
            float hv[4];
            hv[0] = fmaxf(fromL, fmaxf(vm.x, vm.y));
            hv[1] = fmaxf(vm.x,  fmaxf(vm.y, vm.z));
            hv[2] = fmaxf(vm.y,  fmaxf(vm.z, vm.w));
            hv[3] = fmaxf(vm.z,  fmaxf(vm.w, fromR));
            float av[4] = {a.x, a.y, a.z, a.w};
#pragma unroll
            for (int k = 0; k < 4; k++) {
                bool isc = (av[k] == hv[k]);   // 3x3 local max (ties pass)
                unsigned mask = __ballot_sync(0xFFFFFFFFu, isc);
                if (isc) {
                    unsigned u = __float_as_uint(av[k]);
                    unsigned ord = u ^ ((u >> 31) ? 0xFFFFFFFFu : 0x80000000u);
                    int off = wcnt + __popc(mask & ((1u << lane) - 1u));
                    if (off < WSEG)
                        wdst[off] = ((ull)(~ord) << 32) | (unsigned)(yc*Ww + xc + k);
                }
                wcnt = min(wcnt + __popc(mask), WSEG);
            }
            m01 = make_float4(fmaxf(a.x,cur.x), fmaxf(a.y,cur.y),
                              fmaxf(a.z,cur.z), fmaxf(a.w,cur.w));
            a = cur;
            haM = fmaxf(haA, hcur); haA = hcur;
        }
        __half2 hh0 = *(__half2*)&acc0, hh1 = *(__half2*)&acc1;
        float2 f0 = __half22float2(hh0), f1 = __half22float2(hh1);
        s += (f0.x + f0.y) + (f1.x + f1.y);
    }
    if (lane == 0) g_bcnt[map*64 + wg] = wcnt;

    // block reduce (max, sum)
    for (int o = 16; o; o >>= 1) {
        mx = fmaxf(mx, __shfl_down_sync(0xFFFFFFFFu, mx, o));
        s += __shfl_down_sync(0xFFFFFFFFu, s, o);
    }
    if (lane == 0) { sm[wrp] = mx; ss[wrp] = s; }
    __syncthreads();
    if (tid < 8) {
        mx = sm[tid]; s = ss[tid];
        for (int o = 4; o; o >>= 1) {
            mx = fmaxf(mx, __shfl_down_sync(0xFFu, mx, o));
            s += __shfl_down_sync(0xFFu, s, o);
        }
        if (tid == 0) g_part[map*8 + blockIdx.x] = make_float2(mx, s);
    }
}

// ---------------------------------------------------------------------------
// Kernel 2: finalize m, Z, logit cutoff -> key-space threshold
// ---------------------------------------------------------------------------
__global__ void k_finalize() {
    int map = threadIdx.x;
    if (map >= NMAPS) return;
    float m = -3.4e38f, S0 = 0.f;
#pragma unroll
    for (int i = 0; i < 8; i++) {
        float2 p = g_part[map*8 + i];
        m = fmaxf(m, p.x);
        S0 += p.y;
    }
    float Z = S0 * __expf(-m);
    g_m[map] = m; g_Z[map] = Z;
    float cut = m + fmaxf(__logf(Z * (2.0f / (float)HWs)), -4.6051702f);
    unsigned u = __float_as_uint(cut);
    unsigned ord = u ^ ((u >> 31) ? 0xFFFFFFFFu : 0x80000000u);
    // key < cutkey  <=>  value > cut (strict)
    g_cutkey[map] = ((ull)(~ord)) << 32;
}

// ---------------------------------------------------------------------------
// Kernel 3: exact top-K over cut-filtered candidates. Radix round 1
// (bits[63:52]) with round-2 fallback, compact, rank-scatter.
// 64 warp-segments per map, flattened predicated iteration.
// ---------------------------------------------------------------------------
__global__ void __launch_bounds__(512) k_topk(float* __restrict__ out) {
    int map = blockIdx.x;
    int tid = threadIdx.x;
    const ull* cand = g_cand + (size_t)map*CAP;
    ull cutkey = g_cutkey[map];

    __shared__ int bcnt[64];
    __shared__ int hist[4096];
    __shared__ int psum[256];
    __shared__ ull list[2048];
    __shared__ int sh_T, sh_C, sh_H, nlist, sh_tot;
    __shared__ int sh_mode;   // 0: all passing; 1: 12-bit thr; 2: 24-bit thr

    if (tid < 64) bcnt[tid] = g_bcnt[map*64 + tid];
    for (int i = tid; i < 4096; i += 512) hist[i] = 0;
    if (tid == 0) { sh_mode = 0; nlist = 0; }
    __syncthreads();

    // histogram over passing keys
#pragma unroll 4
    for (int i = tid; i < CAP; i += 512) {
        if ((i & (WSEG-1)) < bcnt[i >> 10]) {
            ull key = __ldg(cand + i);
            if (key < cutkey) atomicAdd(&hist[(int)(key >> 52)], 1);
        }
    }
    __syncthreads();
    if (tid < 256) {
        int sg = 0;
        for (int j = 0; j < 16; j++) sg += hist[tid*16 + j];
        psum[tid] = sg;
    }
    __syncthreads();
    if (tid == 0) {
        int run = 0;
        for (int t = 0; t < 256; t++) { int tmp = psum[t]; psum[t] = run; run += tmp; }
        sh_tot = run;
    }
    __syncthreads();
    int ntot = sh_tot;

    unsigned thr24 = 0;
    int T12 = 0;
    if (ntot > Kk) {
        if (tid < 256) {
            int c = psum[tid];
            int hi = 0;
            for (int j = 0; j < 16; j++) hi += hist[tid*16 + j];
            if (c < Kk && c + hi >= Kk) {
                int cc = c;
                for (int j = 0; j < 16; j++) {
                    int h = hist[tid*16 + j];
                    if (cc + h >= Kk) { sh_T = tid*16 + j; sh_C = cc; sh_H = h; break; }
                    cc += h;
                }
            }
        }
        __syncthreads();
        int T = sh_T, C0 = sh_C, HT = sh_H;
        if (C0 + HT <= 2048) {
            if (tid == 0) sh_mode = 1;
            T12 = T;
        } else {
            // round 2: bits [51:40] within bin T (rare)
            __syncthreads();
            for (int i = tid; i < 4096; i += 512) hist[i] = 0;
            __syncthreads();
            for (int i = tid; i < CAP; i += 512) {
                if ((i & (WSEG-1)) < bcnt[i >> 10]) {
                    ull key = __ldg(cand + i);
                    if (key < cutkey && (int)(key >> 52) == T)
                        atomicAdd(&hist[(int)((key >> 40) & 0xFFF)], 1);
                }
            }
            __syncthreads();
            int need = Kk - C0;
            if (tid < 256) {
                int sg = 0;
                for (int j = 0; j < 16; j++) sg += hist[tid*16 + j];
                psum[tid] = sg;
            }
            __syncthreads();
            if (tid == 0) { int run = 0; for (int t = 0; t < 256; t++) { int tmp = psum[t]; psum[t] = run; run += tmp; } }
            __syncthreads();
            if (tid < 256) {
                int c = psum[tid];
                int hi = 0;
                for (int j = 0; j < 16; j++) hi += hist[tid*16 + j];
                if (c < need && c + hi >= need) {
                    int cc = c;
                    for (int j = 0; j < 16; j++) {
                        int h = hist[tid*16 + j];
                        if (cc + h >= need) { sh_T = tid*16 + j; break; }
                        cc += h;
                    }
                }
            }
            if (tid == 0) sh_mode = 2;
            __syncthreads();
            thr24 = ((unsigned)T << 12) | (unsigned)sh_T;
            T12 = T;
        }
    }
    __syncthreads();
    int mode = sh_mode;

    // compact passing keys under the radix threshold
#pragma unroll 4
    for (int i = tid; i < CAP; i += 512) {
        if ((i & (WSEG-1)) < bcnt[i >> 10]) {
            ull key = __ldg(cand + i);
            if (key >= cutkey) continue;
            bool keep;
            if (mode == 0)      keep = true;
            else if (mode == 1) keep = ((int)(key >> 52) <= T12);
            else                keep = ((unsigned)(key >> 40) <= thr24);
            if (keep) {
                int p = atomicAdd(&nlist, 1);
                if (p < 2048) list[p] = key;
            }
        }
    }
    __syncthreads();
    int M = min(nlist, 2048);
    float m = g_m[map];
    float invZ = 1.f / g_Z[map];

    // rank-scatter: rank = #(keys < key); write slot 'rank' directly.
    for (int t = tid; t < M; t += 512) {
        ull k = list[t];
        int rank = 0;
        for (int j = 0; j < M; j++) rank += (list[j] < k);
        if (rank < Kk) {
            unsigned idx = (unsigned)(k & 0xFFFFFFFFu);
            int gx = idx & 511, gy = idx >> 9;
            unsigned ord = ~(unsigned)(k >> 32);
            unsigned u = (ord & 0x80000000u) ? (ord ^ 0x80000000u) : ~ord;
            float v = __uint_as_float(u);
            float sc = __expf(v - m) * invZ;
            int o = map*Kk + rank;
            out[OFF_SCORES + o]       = sc;
            out[OFF_COORDS + o*2]     = (float)gx;
            out[OFF_COORDS + o*2 + 1] = (float)gy;
            out[OFF_VALID  + o]       = 1.f;
            g_selx[o] = gx; g_sely[o] = gy; g_selv[o] = 1;
        }
    }
    if (tid >= M && tid < Kk) {
        int o = map*Kk + tid;
        out[OFF_SCORES + o]       = 0.f;
        out[OFF_COORDS + o*2]     = 0.f;
        out[OFF_COORDS + o*2 + 1] = 0.f;
        out[OFF_VALID  + o]       = 0.f;
        g_selx[o] = 0; g_sely[o] = 0; g_selv[o] = 0;
    }
}

// ---------------------------------------------------------------------------
// Kernel 4: KxK pair edges. grid (40, B*A): 40x parallelism vs one block/ba.
// ---------------------------------------------------------------------------
__global__ void __launch_bounds__(256) k_pairs(const float* __restrict__ paf,
                                               float* __restrict__ out) {
    int ba = blockIdx.y;
    int a  = ba % Aa;
    int b  = ba / Aa;
    int m1 = b*Ss + a, m2 = m1 + 1;
    __shared__ int x1[Kk], y1[Kk], v1[Kk], x2[Kk], y2[Kk], v2[Kk];
    int tid = threadIdx.x;
    if (tid < Kk) {
        x1[tid] = g_selx[m1*Kk + tid]; y1[tid] = g_sely[m1*Kk + tid]; v1[tid] = g_selv[m1*Kk + tid];
        x2[tid] = g_selx[m2*Kk + tid]; y2[tid] = g_sely[m2*Kk + tid]; v2[tid] = g_selv[m2*Kk + tid];
    }
    __syncthreads();
    int idx = blockIdx.x * 256 + tid;
    if (idx >= Kk*Kk) return;
    const float* pafx = paf + (size_t)(ba*2)*HWs;
    const float* pafy = pafx + HWs;
    size_t eb = (size_t)ba * Kk * Kk;
    size_t ib = (size_t)ba * 2 * Kk * Kk;
    int j2 = idx / Kk, j1 = idx - j2*Kk;
    float dx = (float)(x2[j2] - x1[j1]);
    float dy = (float)(y2[j2] - y1[j1]);
    float R = sqrtf(dx*dx + dy*dy);
    bool pv = (R < 20.0f) && v1[j1] && v2[j2];
    float li = 0.f;
    if (pv && R > 0.f) {
        float tvx = dx / R, tvy = dy / R;
        int px1 = x1[j1], py1 = y1[j1], px2 = x2[j2], py2 = y2[j2];
        float acc = 0.f;
#pragma unroll
        for (int t = 0; t < 10; t++) {
            int sx = (px1*(9 - t) + px2*t) / 9;
            int sy = (py1*(9 - t) + py2*t) / 9;
            int off = sy*Ww + sx;
            acc += tvx*__ldg(pafx + off) + tvy*__ldg(pafy + off);
        }
        li = acc * 0.1f;
    }
    out[OFF_EPAF + eb + idx] = li;
    out[OFF_ER   + eb + idx] = pv ? R : 0.f;
    out[OFF_PV   + eb + idx] = pv ? 1.f : 0.f;
    out[OFF_IP   + ib + idx]           = (float)(a*Kk + j1);
    out[OFF_IP   + ib + Kk*Kk + idx]   = (float)((a + 1)*Kk + j2);
}

extern "C" void kernel_launch(void* const* d_in, const int* in_sizes, int n_in,
                              void* d_out, int out_size) {
    const float* pose = (const float*)d_in[0];
    const float* paf  = (const float*)d_in[1];
    float* out = (float*)d_out;
    k_fused   <<<dim3(8, NMAPS), 256>>>(pose);
    k_finalize<<<1, 256>>>();
    k_topk    <<<NMAPS, 512>>>(out);
    k_pairs   <<<dim3((Kk*Kk + 255)/256, Bb*Aa), 256>>>(paf, out);
}